// round 2
// baseline (speedup 1.0000x reference)
#include <cuda_runtime.h>
#include <math.h>

#define NB 2
#define NL 1024
#define NH 8
#define ND 64
#define NDM 768
#define HD 512   /* NH*ND */

// ------------------------- device scratch (no allocation) --------------------
static __device__ float g_q[NB*NL*HD];
static __device__ float g_k[NB*NL*HD];
static __device__ float g_v[NB*NL*HD];
static __device__ float g_ao[NB*NL*HD];
static __device__ float g_uk[NB*NH*NL];
static __device__ float g_Su[NB*NH*NL*33];
static __device__ float g_Ss[NB*NH*NL*33];
static __device__ float g_VrU[NH*33];
static __device__ float g_VrS[NH*33];
static __device__ int   g_t[NL];

// ---------------- 128x128 fp32 SIMT GEMM tile: C = A @ Bw^T (+bias) ----------
// A [M,K] row-major, Bw [N,K] row-major (torch Linear weight layout)
__device__ __forceinline__ void gemm_block128(
    const float* __restrict__ A, const float* __restrict__ Bw,
    float* __restrict__ C, const float* __restrict__ bias,
    int K, int ldc, int m0, int n0, float* As, float* Bs)
{
    const int tid = threadIdx.x;
    const int tx = tid & 15, ty = tid >> 4;

    float acc[8][8];
#pragma unroll
    for (int r = 0; r < 8; r++)
#pragma unroll
        for (int c = 0; c < 8; c++) acc[r][c] = 0.f;

    for (int k0 = 0; k0 < K; k0 += 16) {
#pragma unroll
        for (int s = 0; s < 2; s++) {
            int f = tid + 256*s;
            int row = f >> 2, kg = (f & 3) << 2;
            float4 a = *(const float4*)(A + (size_t)(m0+row)*K + k0 + kg);
            As[(kg+0)*132+row] = a.x; As[(kg+1)*132+row] = a.y;
            As[(kg+2)*132+row] = a.z; As[(kg+3)*132+row] = a.w;
            float4 b = *(const float4*)(Bw + (size_t)(n0+row)*K + k0 + kg);
            Bs[(kg+0)*132+row] = b.x; Bs[(kg+1)*132+row] = b.y;
            Bs[(kg+2)*132+row] = b.z; Bs[(kg+3)*132+row] = b.w;
        }
        __syncthreads();
#pragma unroll
        for (int kk = 0; kk < 16; kk++) {
            float af[8], bf[8];
            *(float4*)(af)   = *(const float4*)(As + kk*132 + ty*8);
            *(float4*)(af+4) = *(const float4*)(As + kk*132 + ty*8 + 4);
            *(float4*)(bf)   = *(const float4*)(Bs + kk*132 + tx*8);
            *(float4*)(bf+4) = *(const float4*)(Bs + kk*132 + tx*8 + 4);
#pragma unroll
            for (int r = 0; r < 8; r++)
#pragma unroll
                for (int c = 0; c < 8; c++)
                    acc[r][c] += af[r]*bf[c];
        }
        __syncthreads();
    }

#pragma unroll
    for (int r = 0; r < 8; r++) {
        int m = m0 + ty*8 + r;
#pragma unroll
        for (int cg = 0; cg < 2; cg++) {
            int n = n0 + tx*8 + cg*4;
            float4 v;
            v.x = acc[r][cg*4+0]; v.y = acc[r][cg*4+1];
            v.z = acc[r][cg*4+2]; v.w = acc[r][cg*4+3];
            if (bias) { v.x += bias[n]; v.y += bias[n+1]; v.z += bias[n+2]; v.w += bias[n+3]; }
            *(float4*)(C + (size_t)m*ldc + n) = v;
        }
    }
}

__global__ __launch_bounds__(256)
void gemm_qkv_kernel(const float* __restrict__ x,
                     const float* __restrict__ Wq,
                     const float* __restrict__ Wk,
                     const float* __restrict__ Wv)
{
    __shared__ float As[16*132], Bs[16*132];
    const float* W; float* C;
    if (blockIdx.z == 0)      { W = Wq; C = g_q; }
    else if (blockIdx.z == 1) { W = Wk; C = g_k; }
    else                      { W = Wv; C = g_v; }
    gemm_block128(x, W, C, 0, NDM, HD, blockIdx.y*128, blockIdx.x*128, As, Bs);
}

__global__ __launch_bounds__(256)
void gemm_out_kernel(const float* __restrict__ Wo,
                     const float* __restrict__ bo,
                     float* __restrict__ out)
{
    __shared__ float As[16*132], Bs[16*132];
    gemm_block128(g_ao, Wo, out, bo, HD, NDM, blockIdx.y*128, blockIdx.x*128, As, Bs);
}

// ---------------- uk[b,h,j] = sum_d u_bias[h,d] * k[b,j,h,d] -----------------
__global__ __launch_bounds__(256)
void uk_kernel(const float* __restrict__ u_bias)
{
    int idx = blockIdx.x*256 + threadIdx.x;       // 0..16383
    int bh = idx >> 10, j = idx & 1023;
    int b = bh >> 3, hh = bh & 7;
    const float* kr = g_k + (size_t)(b*NL + j)*HD + hh*ND;
    const float* ub = u_bias + hh*ND;
    float s = 0.f;
#pragma unroll
    for (int d = 0; d < ND; d += 4) {
        float4 kv = *(const float4*)(kr + d);
        float4 uv = *(const float4*)(ub + d);
        s += kv.x*uv.x + kv.y*uv.y + kv.z*uv.z + kv.w*uv.w;
    }
    g_uk[idx] = s;
}

// ---------------- prep: center widths, threshold table, vr suffix sums -------
__global__ void prep_kernel(const float* __restrict__ v_bias,
                            const float* __restrict__ w_pos)
{
    __shared__ float cw[32];
    __shared__ float vws[512];
    const int tid = threadIdx.x;
    if (tid < 32) {
        float pr = expf(logf((float)(NL+1) * 0.5f) / 32.f);
        cw[tid] = powf(pr, (float)(tid+1));
    }
    __syncthreads();
    // t(a) = min{f : a <= cw[f]}, else 32
    for (int a = tid; a < NL; a += 256) {
        int t = 32;
        for (int f = 0; f < 32; f++)
            if ((float)a <= cw[f]) { t = f; break; }
        g_t[a] = t;
    }
    // vw[h,n] = sum_d v_bias[h,d] * w_pos[h,d,n]
    for (int idx = tid; idx < 512; idx += 256) {
        int hh = idx >> 6, n = idx & 63;
        float s = 0.f;
        for (int d = 0; d < 64; d++)
            s += v_bias[hh*64 + d] * w_pos[hh*4096 + d*64 + n];
        vws[idx] = s;
    }
    __syncthreads();
    if (tid < 16) {
        int hh = tid >> 1, half = tid & 1;
        float* dst = (half ? g_VrS : g_VrU) + hh*33;
        const float* src = vws + hh*64 + half*32;
        float run = 0.f;
        dst[32] = 0.f;
        for (int f = 31; f >= 0; f--) { run += src[f]; dst[f] = run; }
    }
}

// ---------------- qw = q @ w_pos[h] ; per-row suffix sums (+vr folded) -------
// block: 32 q-rows of one (b,h). grid (32, 8, 2)
__global__ __launch_bounds__(256)
void qw_kernel(const float* __restrict__ w_pos)
{
    __shared__ float wp[64*65];   // [d][n]
    __shared__ float qs[32*65];   // [row][d]
    __shared__ float qw[32*65];   // [row][n]
    const int tid = threadIdx.x;
    const int ic = blockIdx.x, hh = blockIdx.y, b = blockIdx.z;
    const int i0 = ic*32;

    for (int idx = tid; idx < 4096; idx += 256)
        wp[(idx >> 6)*65 + (idx & 63)] = w_pos[hh*4096 + idx];
    for (int idx = tid; idx < 2048; idx += 256) {
        int row = idx >> 6, d = idx & 63;
        qs[row*65 + d] = g_q[(size_t)(b*NL + i0 + row)*HD + hh*ND + d];
    }
    __syncthreads();
    {
        int row = tid >> 3;
        int nb = (tid & 7) << 3;
        for (int nn = 0; nn < 8; nn++) {
            int n = nb + nn;
            float acc = 0.f;
#pragma unroll 8
            for (int d = 0; d < 64; d++)
                acc += qs[row*65 + d] * wp[d*65 + n];
            qw[row*65 + n] = acc;
        }
    }
    __syncthreads();
    if (tid < 64) {
        int row = tid >> 1, half = tid & 1;
        size_t base = (size_t)((b*NH + hh)*NL + i0 + row)*33;
        const float* vr = (half ? g_VrS : g_VrU) + hh*33;
        float* dst = (half ? g_Ss : g_Su) + base;
        const float* src = qw + row*65 + half*32;
        float run = 0.f;
        dst[32] = vr[32];
        for (int f = 31; f >= 0; f--) {
            run += src[f];
            dst[f] = run + vr[f];
        }
    }
}

// ---------------- flash attention with factored relative-position bias -------
#define OFF_QT 0        /* [64][132]  */
#define OFF_KT 8448     /* [64][132]  */
#define OFF_V  16896    /* [128][68]  */
#define OFF_P  25600    /* [128][132] */
#define OFF_SU 42496    /* [128][33]  */
#define OFF_SS 46720    /* [128][33]  */
#define OFF_UK 50944    /* [1024]     */
#define OFF_T  51968    /* [1024] int */
#define ATTN_SMEM_FLOATS 52992
#define ATTN_SMEM (ATTN_SMEM_FLOATS*4)

__global__ __launch_bounds__(256, 1)
void attn_kernel()
{
    extern __shared__ float sm[];
    float* QsT = sm + OFF_QT;
    float* KsT = sm + OFF_KT;
    float* Vs  = sm + OFF_V;
    float* Ps  = sm + OFF_P;
    float* SuS = sm + OFF_SU;
    float* SsS = sm + OFF_SS;
    float* uks = sm + OFF_UK;
    int*   ts  = (int*)(sm + OFF_T);

    const int tid = threadIdx.x;
    const int tx = tid & 15, ty = tid >> 4;
    const int it = blockIdx.x, hh = blockIdx.y, b = blockIdx.z;
    const int i0 = it * 128;
    const int bh = b*NH + hh;
    const float scale = 0.125f;

    // prologue: Q tile (transposed), suffix tables, uk row, threshold table
    {
        const float* qb = g_q + (size_t)(b*NL + i0)*HD + hh*ND;
        for (int idx = tid; idx < 128*64; idx += 256) {
            int row = idx >> 6, d = idx & 63;
            QsT[d*132 + row] = qb[(size_t)row*HD + d];
        }
    }
    for (int idx = tid; idx < 128*33; idx += 256) {
        SuS[idx] = g_Su[(size_t)(bh*NL + i0)*33 + idx];
        SsS[idx] = g_Ss[(size_t)(bh*NL + i0)*33 + idx];
    }
    for (int idx = tid; idx < NL; idx += 256) {
        uks[idx] = g_uk[bh*NL + idx];
        ts[idx]  = g_t[idx];
    }

    float m_[8], l_[8], oa[8][4];
#pragma unroll
    for (int r = 0; r < 8; r++) {
        m_[r] = -1e30f; l_[r] = 0.f;
#pragma unroll
        for (int c = 0; c < 4; c++) oa[r][c] = 0.f;
    }

    for (int jc = 0; jc < 8; jc++) {
        const int j0 = jc * 128;
        __syncthreads();   // previous chunk's GEMM2 done before K/V overwrite
        {
            const float* kb = g_k + (size_t)(b*NL + j0)*HD + hh*ND;
            for (int idx = tid; idx < 128*64; idx += 256) {
                int row = idx >> 6, d = idx & 63;
                KsT[d*132 + row] = kb[(size_t)row*HD + d];
            }
            const float* vb = g_v + (size_t)(b*NL + j0)*HD + hh*ND;
            for (int idx = tid; idx < 128*16; idx += 256) {
                int row = idx >> 4, g4 = (idx & 15) << 2;
                float4 v = *(const float4*)(vb + (size_t)row*HD + g4);
                *(float4*)(Vs + row*68 + g4) = v;
            }
        }
        __syncthreads();

        // GEMM1: S = Q @ K^T
        float s[8][8];
#pragma unroll
        for (int r = 0; r < 8; r++)
#pragma unroll
            for (int c = 0; c < 8; c++) s[r][c] = 0.f;
#pragma unroll 4
        for (int kk = 0; kk < 64; kk++) {
            float af[8], bf[8];
            *(float4*)(af)   = *(const float4*)(QsT + kk*132 + ty*8);
            *(float4*)(af+4) = *(const float4*)(QsT + kk*132 + ty*8 + 4);
            *(float4*)(bf)   = *(const float4*)(KsT + kk*132 + tx*8);
            *(float4*)(bf+4) = *(const float4*)(KsT + kk*132 + tx*8 + 4);
#pragma unroll
            for (int r = 0; r < 8; r++)
#pragma unroll
                for (int c = 0; c < 8; c++)
                    s[r][c] += af[r]*bf[c];
        }

        // bias + online softmax
#pragma unroll
        for (int r = 0; r < 8; r++) {
            int il = ty*8 + r;
            int ig = i0 + il;
            float p[8];
            float mx = -1e30f;
#pragma unroll
            for (int c = 0; c < 8; c++) {
                int jg = j0 + tx*8 + c;
                int dd = jg - ig;
                int a  = dd < 0 ? -dd : dd;
                int t  = ts[a];
                float su = SuS[il*33 + t];
                float ss = SsS[il*33 + t];
                float bias = su + (dd > 0 ? ss : (dd < 0 ? -ss : 0.f)) + uks[jg];
                float val = (s[r][c] + bias) * scale;
                p[c] = val;
                mx = fmaxf(mx, val);
            }
#pragma unroll
            for (int o = 8; o >= 1; o >>= 1)
                mx = fmaxf(mx, __shfl_xor_sync(0xffffffffu, mx, o, 16));
            float mnew = fmaxf(m_[r], mx);
            float alpha = __expf(m_[r] - mnew);
            float rs = 0.f;
#pragma unroll
            for (int c = 0; c < 8; c++) { p[c] = __expf(p[c] - mnew); rs += p[c]; }
#pragma unroll
            for (int o = 8; o >= 1; o >>= 1)
                rs += __shfl_xor_sync(0xffffffffu, rs, o, 16);
            l_[r] = l_[r]*alpha + rs;
            m_[r] = mnew;
#pragma unroll
            for (int c = 0; c < 4; c++) oa[r][c] *= alpha;
            float4 v0, v1;
            v0.x = p[0]; v0.y = p[1]; v0.z = p[2]; v0.w = p[3];
            v1.x = p[4]; v1.y = p[5]; v1.z = p[6]; v1.w = p[7];
            *(float4*)(Ps + il*132 + tx*8)     = v0;
            *(float4*)(Ps + il*132 + tx*8 + 4) = v1;
        }
        __syncthreads();

        // GEMM2: O += P @ V   (P rows broadcast across tx)
#pragma unroll 4
        for (int jj = 0; jj < 128; jj++) {
            float bf[4];
            *(float4*)bf = *(const float4*)(Vs + jj*68 + tx*4);
#pragma unroll
            for (int r = 0; r < 8; r++) {
                float a = Ps[(ty*8 + r)*132 + jj];
                oa[r][0] += a*bf[0]; oa[r][1] += a*bf[1];
                oa[r][2] += a*bf[2]; oa[r][3] += a*bf[3];
            }
        }
    }

    // epilogue: normalize and store
    float* ob = g_ao + (size_t)(b*NL + i0)*HD + hh*ND;
#pragma unroll
    for (int r = 0; r < 8; r++) {
        float inv = 1.f / l_[r];
        float4 v;
        v.x = oa[r][0]*inv; v.y = oa[r][1]*inv;
        v.z = oa[r][2]*inv; v.w = oa[r][3]*inv;
        *(float4*)(ob + (size_t)(ty*8 + r)*HD + tx*4) = v;
    }
}

// ----------------------------------------------------------------------------
extern "C" void kernel_launch(void* const* d_in, const int* in_sizes, int n_in,
                              void* d_out, int out_size)
{
    const float* x      = (const float*)d_in[0];
    const float* Wq     = (const float*)d_in[1];
    const float* Wk     = (const float*)d_in[2];
    const float* Wv     = (const float*)d_in[3];
    const float* Wo     = (const float*)d_in[4];
    const float* bo     = (const float*)d_in[5];
    const float* u_bias = (const float*)d_in[6];
    const float* v_bias = (const float*)d_in[7];
    const float* w_pos  = (const float*)d_in[8];
    float* out = (float*)d_out;

    cudaFuncSetAttribute(attn_kernel,
                         cudaFuncAttributeMaxDynamicSharedMemorySize, ATTN_SMEM);

    gemm_qkv_kernel<<<dim3(4, 16, 3), 256>>>(x, Wq, Wk, Wv);
    uk_kernel<<<64, 256>>>(u_bias);
    prep_kernel<<<1, 256>>>(v_bias, w_pos);
    qw_kernel<<<dim3(32, 8, 2), 256>>>(w_pos);
    attn_kernel<<<dim3(8, 8, 2), 256, ATTN_SMEM>>>();
    gemm_out_kernel<<<dim3(6, 16), 256>>>(Wo, bo, out);
}

// round 4
// speedup vs baseline: 1.3233x; 1.3233x over previous
#include <cuda_runtime.h>
#include <cuda_bf16.h>
#include <math.h>
#include <stdint.h>

#define NB 2
#define NL 1024
#define NH 8
#define ND 64
#define NDM 768
#define HD 512        /* NH*ND */
#define QLD 2048      /* g_qkv row stride: Q|K|V|QW */
#define KAUG_X 2304   /* 3*768 */
#define KAUG_O 1536   /* 3*512 */

// ------------------------- device scratch (no allocation) --------------------
static __device__ __align__(16) __nv_bfloat16 g_Aaug [NB*NL*KAUG_X];   // x hi|lo|hi
static __device__ __align__(16) __nv_bfloat16 g_Waug [2048*KAUG_X];    // Wq|Wk|Wv|W2 hi|hi|lo
static __device__ __align__(16) __nv_bfloat16 g_AOaug[NB*NL*KAUG_O];   // ao hi|lo|hi
static __device__ __align__(16) __nv_bfloat16 g_WOaug[NDM*KAUG_O];     // Wo hi|hi|lo
static __device__ __align__(16) float g_W2 [HD*NDM];                   // folded Wq^T@wpos
static __device__ __align__(16) float g_qkv[NB*NL*QLD];                // Q|K|V|QW fp32
static __device__ __align__(16) float g_ao [NB*NL*HD];
static __device__ __align__(16) float g_uk [NB*NH*NL];
static __device__ __align__(16) float g_Su [NB*NH*NL*33];
static __device__ __align__(16) float g_Ss [NB*NH*NL*33];
static __device__ __align__(16) float g_VrU[NH*33];
static __device__ __align__(16) float g_VrS[NH*33];
static __device__ int   g_t[NL];

// ------------------------- conversion kernels --------------------------------
__device__ __forceinline__ void split_hl(float v, __nv_bfloat16& h, __nv_bfloat16& l) {
    h = __float2bfloat16(v);
    l = __float2bfloat16(v - __bfloat162float(h));
}

__global__ void conv_x_kernel(const float* __restrict__ x) {   // grid 2048
    int row = blockIdx.x;
    const float* src = x + (size_t)row * NDM;
    __nv_bfloat16* dst = g_Aaug + (size_t)row * KAUG_X;
    for (int c = threadIdx.x; c < NDM; c += 256) {
        __nv_bfloat16 h, l; split_hl(src[c], h, l);
        dst[c] = h; dst[NDM + c] = l; dst[2*NDM + c] = h;
    }
}

__global__ void fold_w2_kernel(const float* __restrict__ Wq,
                               const float* __restrict__ w_pos) { // grid 512
    __shared__ float wp[64];
    int hn = blockIdx.x, h = hn >> 6, n = hn & 63;
    if (threadIdx.x < 64) wp[threadIdx.x] = w_pos[h*4096 + threadIdx.x*64 + n];
    __syncthreads();
    for (int m = threadIdx.x; m < NDM; m += 256) {
        float s = 0.f;
#pragma unroll 16
        for (int d = 0; d < 64; d++)
            s += Wq[(size_t)(h*64 + d)*NDM + m] * wp[d];
        g_W2[(size_t)hn*NDM + m] = s;
    }
}

__global__ void conv_w_kernel(const float* __restrict__ Wq,
                              const float* __restrict__ Wk,
                              const float* __restrict__ Wv) {  // grid 2048
    int r = blockIdx.x;
    const float* src;
    if (r < 512)        src = Wq + (size_t)r * NDM;
    else if (r < 1024)  src = Wk + (size_t)(r-512) * NDM;
    else if (r < 1536)  src = Wv + (size_t)(r-1024) * NDM;
    else                src = g_W2 + (size_t)(r-1536) * NDM;
    __nv_bfloat16* dst = g_Waug + (size_t)r * KAUG_X;
    for (int c = threadIdx.x; c < NDM; c += 256) {
        __nv_bfloat16 h, l; split_hl(src[c], h, l);
        dst[c] = h; dst[NDM + c] = h; dst[2*NDM + c] = l;
    }
}

__global__ void conv_ao_kernel() {  // grid 2048
    int row = blockIdx.x;
    const float* src = g_ao + (size_t)row * HD;
    __nv_bfloat16* dst = g_AOaug + (size_t)row * KAUG_O;
    for (int c = threadIdx.x; c < HD; c += 256) {
        __nv_bfloat16 h, l; split_hl(src[c], h, l);
        dst[c] = h; dst[HD + c] = l; dst[2*HD + c] = h;
    }
}

__global__ void conv_wo_kernel(const float* __restrict__ Wo) {  // grid 768
    int r = blockIdx.x;
    const float* src = Wo + (size_t)r * HD;
    __nv_bfloat16* dst = g_WOaug + (size_t)r * KAUG_O;
    for (int c = threadIdx.x; c < HD; c += 256) {
        __nv_bfloat16 h, l; split_hl(src[c], h, l);
        dst[c] = h; dst[HD + c] = h; dst[2*HD + c] = l;
    }
}

// ------------------------- mma.sync bf16 GEMM: C = A @ Bw^T ------------------
// 128x128 tile, K-chunks of 32, cp.async double-buffered, 8 warps (2m x 4n).
#define BM 128
#define BN 128
#define BK 32
#define GSTR 40   /* smem row stride in bf16 elements (80B, 16B-aligned, ldmatrix conflict-free) */

__device__ __forceinline__ void mma16816(float* c, const uint32_t* a, const uint32_t* b) {
    asm volatile(
        "mma.sync.aligned.m16n8k16.row.col.f32.bf16.bf16.f32 "
        "{%0,%1,%2,%3}, {%4,%5,%6,%7}, {%8,%9}, {%0,%1,%2,%3};"
        : "+f"(c[0]), "+f"(c[1]), "+f"(c[2]), "+f"(c[3])
        : "r"(a[0]), "r"(a[1]), "r"(a[2]), "r"(a[3]), "r"(b[0]), "r"(b[1]));
}

__global__ __launch_bounds__(256, 1)
void gemm_mma(int which, const float* __restrict__ bias, float* __restrict__ Cout)
{
    __shared__ __nv_bfloat16 sA[2][BM*GSTR];
    __shared__ __nv_bfloat16 sB[2][BN*GSTR];

    const int tid = threadIdx.x;
    const int wid = tid >> 5, lane = tid & 31;
    const int wm = wid >> 2, wn = wid & 3;          // 2 x 4 warp grid
    const int m0 = blockIdx.y * BM, n0 = blockIdx.x * BN;

    const __nv_bfloat16 *A, *Bw;
    float* C; int Kaug, Ntot;
    if (which == 0) { A = g_Aaug;  Bw = g_Waug;  C = g_qkv; Kaug = KAUG_X; Ntot = QLD; }
    else            { A = g_AOaug; Bw = g_WOaug; C = Cout;  Kaug = KAUG_O; Ntot = NDM; }
    const int nk = Kaug / BK;

    const int ldrow = tid >> 2, ldg = tid & 3;      // 4 x 16B per 64B row-chunk

    auto prefetch = [&](int c) {
        int p = c & 1;
        {
            const __nv_bfloat16* Ab = A + (size_t)(m0 + ldrow) * Kaug + c*BK + ldg*8;
#pragma unroll
            for (int s = 0; s < 2; s++) {
                uint32_t dst = (uint32_t)__cvta_generic_to_shared(
                    &sA[p][(ldrow + s*64)*GSTR + ldg*8]);
                const void* src = Ab + (size_t)(s*64) * Kaug;
                asm volatile("cp.async.cg.shared.global [%0], [%1], 16;" :: "r"(dst), "l"(src));
            }
        }
        {
            const __nv_bfloat16* Bb = Bw + (size_t)(n0 + ldrow) * Kaug + c*BK + ldg*8;
#pragma unroll
            for (int s = 0; s < 2; s++) {
                uint32_t dst = (uint32_t)__cvta_generic_to_shared(
                    &sB[p][(ldrow + s*64)*GSTR + ldg*8]);
                const void* src = Bb + (size_t)(s*64) * Kaug;
                asm volatile("cp.async.cg.shared.global [%0], [%1], 16;" :: "r"(dst), "l"(src));
            }
        }
        asm volatile("cp.async.commit_group;" ::: "memory");
    };

    float acc[4][4][4];
#pragma unroll
    for (int i = 0; i < 4; i++)
#pragma unroll
        for (int j = 0; j < 4; j++)
#pragma unroll
            for (int r = 0; r < 4; r++) acc[i][j][r] = 0.f;

    prefetch(0);

    for (int c = 0; c < nk; c++) {
        int p = c & 1;
        if (c + 1 < nk) {
            prefetch(c + 1);
            asm volatile("cp.async.wait_group 1;" ::: "memory");
        } else {
            asm volatile("cp.async.wait_group 0;" ::: "memory");
        }
        __syncthreads();

        uint32_t aB = (uint32_t)__cvta_generic_to_shared(&sA[p][0]);
        uint32_t bB = (uint32_t)__cvta_generic_to_shared(&sB[p][0]);

#pragma unroll
        for (int ks = 0; ks < 2; ks++) {
            uint32_t a[4][4];
#pragma unroll
            for (int i = 0; i < 4; i++) {
                uint32_t addr = aB + (uint32_t)(
                    ((wm*64 + i*16 + (lane & 15))*GSTR + ((lane >> 4)*8) + ks*16) * 2);
                asm volatile("ldmatrix.sync.aligned.m8n8.x4.shared.b16 {%0,%1,%2,%3}, [%4];"
                    : "=r"(a[i][0]), "=r"(a[i][1]), "=r"(a[i][2]), "=r"(a[i][3]) : "r"(addr));
            }
            uint32_t b[4][2];
#pragma unroll
            for (int jp = 0; jp < 2; jp++) {
                uint32_t addr = bB + (uint32_t)(
                    ((wn*32 + jp*16 + (lane & 7) + ((lane >> 4) << 3))*GSTR
                     + (((lane >> 3) & 1) << 3) + ks*16) * 2);
                asm volatile("ldmatrix.sync.aligned.m8n8.x4.shared.b16 {%0,%1,%2,%3}, [%4];"
                    : "=r"(b[2*jp][0]), "=r"(b[2*jp][1]),
                      "=r"(b[2*jp+1][0]), "=r"(b[2*jp+1][1]) : "r"(addr));
            }
#pragma unroll
            for (int i = 0; i < 4; i++)
#pragma unroll
                for (int j = 0; j < 4; j++)
                    mma16816(acc[i][j], a[i], b[j]);
        }
        __syncthreads();
    }

    // epilogue
#pragma unroll
    for (int i = 0; i < 4; i++) {
        int r0 = m0 + wm*64 + i*16 + (lane >> 2);
#pragma unroll
        for (int j = 0; j < 4; j++) {
            int col = n0 + wn*32 + j*8 + (lane & 3)*2;
            float b0 = 0.f, b1 = 0.f;
            if (bias) { b0 = bias[col]; b1 = bias[col+1]; }
            float2 v0 = make_float2(acc[i][j][0] + b0, acc[i][j][1] + b1);
            float2 v1 = make_float2(acc[i][j][2] + b0, acc[i][j][3] + b1);
            *(float2*)(C + (size_t)r0 * Ntot + col)       = v0;
            *(float2*)(C + (size_t)(r0 + 8) * Ntot + col) = v1;
        }
    }
}

// ---------------- uk[b,h,j] = sum_d u_bias[h,d] * k[b,j,h,d] -----------------
__global__ __launch_bounds__(256)
void uk_kernel(const float* __restrict__ u_bias)
{
    int idx = blockIdx.x*256 + threadIdx.x;       // 0..16383
    int bh = idx >> 10, j = idx & 1023;
    int b = bh >> 3, hh = bh & 7;
    const float* kr = g_qkv + (size_t)(b*NL + j)*QLD + 512 + hh*ND;
    const float* ub = u_bias + hh*ND;
    float s = 0.f;
#pragma unroll
    for (int d = 0; d < ND; d += 4) {
        float4 kv = *(const float4*)(kr + d);
        float4 uv = *(const float4*)(ub + d);
        s += kv.x*uv.x + kv.y*uv.y + kv.z*uv.z + kv.w*uv.w;
    }
    g_uk[idx] = s;
}

// ---------------- prep: center widths, threshold table, vr suffix sums -------
__global__ void prep_kernel(const float* __restrict__ v_bias,
                            const float* __restrict__ w_pos)
{
    __shared__ float cw[32];
    __shared__ float vws[512];
    const int tid = threadIdx.x;
    if (tid < 32) {
        float pr = expf(logf((float)(NL+1) * 0.5f) / 32.f);
        cw[tid] = powf(pr, (float)(tid+1));
    }
    __syncthreads();
    for (int a = tid; a < NL; a += 256) {
        int t = 32;
        for (int f = 0; f < 32; f++)
            if ((float)a <= cw[f]) { t = f; break; }
        g_t[a] = t;
    }
    for (int idx = tid; idx < 512; idx += 256) {
        int hh = idx >> 6, n = idx & 63;
        float s = 0.f;
        for (int d = 0; d < 64; d++)
            s += v_bias[hh*64 + d] * w_pos[hh*4096 + d*64 + n];
        vws[idx] = s;
    }
    __syncthreads();
    if (tid < 16) {
        int hh = tid >> 1, half = tid & 1;
        float* dst = (half ? g_VrS : g_VrU) + hh*33;
        const float* src = vws + hh*64 + half*32;
        float run = 0.f;
        dst[32] = 0.f;
        for (int f = 31; f >= 0; f--) { run += src[f]; dst[f] = run; }
    }
}

// ---------------- suffix sums of qw rows (+vr folded), warp-per-row ----------
__global__ __launch_bounds__(256)
void suffix_kernel()
{
    int gw = blockIdx.x*8 + (threadIdx.x >> 5);   // 0..32767
    int lane = threadIdx.x & 31;
    int half = gw & 1;
    int pair = gw >> 1;                            // 0..16383
    int h = pair & 7;
    int row = pair >> 3;                           // b*1024+i, 0..2047
    int b = row >> 10, i = row & 1023;

    float v = g_qkv[(size_t)row*QLD + 1536 + h*64 + half*32 + lane];
#pragma unroll
    for (int o = 1; o < 32; o <<= 1) {
        float t = __shfl_down_sync(0xffffffffu, v, o);
        if (lane + o < 32) v += t;
    }
    const float* vr = (half ? g_VrS : g_VrU) + h*33;
    float* dst = (half ? g_Ss : g_Su) + (size_t)((b*NH + h)*NL + i)*33;
    dst[lane] = v + vr[lane];
    if (lane == 0) dst[32] = vr[32];
}

// ---------------- flash attention with factored relative-position bias -------
#define OFF_QT 0        /* [64][132]  */
#define OFF_KT 8448     /* [64][132]  */
#define OFF_V  16896    /* [128][68]  */
#define OFF_P  25600    /* [128][132] */
#define OFF_SU 42496    /* [128][33]  */
#define OFF_SS 46720    /* [128][33]  */
#define OFF_UK 50944    /* [1024]     */
#define OFF_T  51968    /* [1024] int */
#define ATTN_SMEM_FLOATS 52992
#define ATTN_SMEM (ATTN_SMEM_FLOATS*4)

__global__ __launch_bounds__(256, 1)
void attn_kernel()
{
    extern __shared__ float sm[];
    float* QsT = sm + OFF_QT;
    float* KsT = sm + OFF_KT;
    float* Vs  = sm + OFF_V;
    float* Ps  = sm + OFF_P;
    float* SuS = sm + OFF_SU;
    float* SsS = sm + OFF_SS;
    float* uks = sm + OFF_UK;
    int*   ts  = (int*)(sm + OFF_T);

    const int tid = threadIdx.x;
    const int tx = tid & 15, ty = tid >> 4;
    const int it = blockIdx.x, hh = blockIdx.y, b = blockIdx.z;
    const int i0 = it * 128;
    const int bh = b*NH + hh;
    const float scale = 0.125f;

    {
        const float* qb = g_qkv + (size_t)(b*NL + i0)*QLD + hh*ND;
        for (int idx = tid; idx < 128*64; idx += 256) {
            int row = idx >> 6, d = idx & 63;
            QsT[d*132 + row] = qb[(size_t)row*QLD + d];
        }
    }
    for (int idx = tid; idx < 128*33; idx += 256) {
        SuS[idx] = g_Su[(size_t)(bh*NL + i0)*33 + idx];
        SsS[idx] = g_Ss[(size_t)(bh*NL + i0)*33 + idx];
    }
    for (int idx = tid; idx < NL; idx += 256) {
        uks[idx] = g_uk[bh*NL + idx];
        ts[idx]  = g_t[idx];
    }

    float m_[8], l_[8], oa[8][4];
#pragma unroll
    for (int r = 0; r < 8; r++) {
        m_[r] = -1e30f; l_[r] = 0.f;
#pragma unroll
        for (int c = 0; c < 4; c++) oa[r][c] = 0.f;
    }

    for (int jc = 0; jc < 8; jc++) {
        const int j0 = jc * 128;
        __syncthreads();
        {
            const float* kb = g_qkv + (size_t)(b*NL + j0)*QLD + 512 + hh*ND;
            for (int idx = tid; idx < 128*64; idx += 256) {
                int row = idx >> 6, d = idx & 63;
                KsT[d*132 + row] = kb[(size_t)row*QLD + d];
            }
            const float* vb = g_qkv + (size_t)(b*NL + j0)*QLD + 1024 + hh*ND;
            for (int idx = tid; idx < 128*16; idx += 256) {
                int row = idx >> 4, g4 = (idx & 15) << 2;
                float4 v = *(const float4*)(vb + (size_t)row*QLD + g4);
                *(float4*)(Vs + row*68 + g4) = v;
            }
        }
        __syncthreads();

        float s[8][8];
#pragma unroll
        for (int r = 0; r < 8; r++)
#pragma unroll
            for (int c = 0; c < 8; c++) s[r][c] = 0.f;
#pragma unroll 4
        for (int kk = 0; kk < 64; kk++) {
            float af[8], bf[8];
            *(float4*)(af)   = *(const float4*)(QsT + kk*132 + ty*8);
            *(float4*)(af+4) = *(const float4*)(QsT + kk*132 + ty*8 + 4);
            *(float4*)(bf)   = *(const float4*)(KsT + kk*132 + tx*8);
            *(float4*)(bf+4) = *(const float4*)(KsT + kk*132 + tx*8 + 4);
#pragma unroll
            for (int r = 0; r < 8; r++)
#pragma unroll
                for (int c = 0; c < 8; c++)
                    s[r][c] += af[r]*bf[c];
        }

#pragma unroll
        for (int r = 0; r < 8; r++) {
            int il = ty*8 + r;
            int ig = i0 + il;
            float p[8];
            float mx = -1e30f;
#pragma unroll
            for (int c = 0; c < 8; c++) {
                int jg = j0 + tx*8 + c;
                int dd = jg - ig;
                int a  = dd < 0 ? -dd : dd;
                int t  = ts[a];
                float su = SuS[il*33 + t];
                float ss = SsS[il*33 + t];
                float bias = su + (dd > 0 ? ss : (dd < 0 ? -ss : 0.f)) + uks[jg];
                float val = (s[r][c] + bias) * scale;
                p[c] = val;
                mx = fmaxf(mx, val);
            }
#pragma unroll
            for (int o = 8; o >= 1; o >>= 1)
                mx = fmaxf(mx, __shfl_xor_sync(0xffffffffu, mx, o, 16));
            float mnew = fmaxf(m_[r], mx);
            float alpha = __expf(m_[r] - mnew);
            float rs = 0.f;
#pragma unroll
            for (int c = 0; c < 8; c++) { p[c] = __expf(p[c] - mnew); rs += p[c]; }
#pragma unroll
            for (int o = 8; o >= 1; o >>= 1)
                rs += __shfl_xor_sync(0xffffffffu, rs, o, 16);
            l_[r] = l_[r]*alpha + rs;
            m_[r] = mnew;
#pragma unroll
            for (int c = 0; c < 4; c++) oa[r][c] *= alpha;
            float4 v0, v1;
            v0.x = p[0]; v0.y = p[1]; v0.z = p[2]; v0.w = p[3];
            v1.x = p[4]; v1.y = p[5]; v1.z = p[6]; v1.w = p[7];
            *(float4*)(Ps + il*132 + tx*8)     = v0;
            *(float4*)(Ps + il*132 + tx*8 + 4) = v1;
        }
        __syncthreads();

#pragma unroll 4
        for (int jj = 0; jj < 128; jj++) {
            float bf[4];
            *(float4*)bf = *(const float4*)(Vs + jj*68 + tx*4);
#pragma unroll
            for (int r = 0; r < 8; r++) {
                float a = Ps[(ty*8 + r)*132 + jj];
                oa[r][0] += a*bf[0]; oa[r][1] += a*bf[1];
                oa[r][2] += a*bf[2]; oa[r][3] += a*bf[3];
            }
        }
    }

    float* ob = g_ao + (size_t)(b*NL + i0)*HD + hh*ND;
#pragma unroll
    for (int r = 0; r < 8; r++) {
        float inv = 1.f / l_[r];
        float4 v;
        v.x = oa[r][0]*inv; v.y = oa[r][1]*inv;
        v.z = oa[r][2]*inv; v.w = oa[r][3]*inv;
        *(float4*)(ob + (size_t)(ty*8 + r)*HD + tx*4) = v;
    }
}

// ----------------------------------------------------------------------------
extern "C" void kernel_launch(void* const* d_in, const int* in_sizes, int n_in,
                              void* d_out, int out_size)
{
    const float* x      = (const float*)d_in[0];
    const float* Wq     = (const float*)d_in[1];
    const float* Wk     = (const float*)d_in[2];
    const float* Wv     = (const float*)d_in[3];
    const float* Wo     = (const float*)d_in[4];
    const float* bo     = (const float*)d_in[5];
    const float* u_bias = (const float*)d_in[6];
    const float* v_bias = (const float*)d_in[7];
    const float* w_pos  = (const float*)d_in[8];
    float* out = (float*)d_out;

    cudaFuncSetAttribute(attn_kernel,
                         cudaFuncAttributeMaxDynamicSharedMemorySize, ATTN_SMEM);

    fold_w2_kernel<<<512, 256>>>(Wq, w_pos);
    conv_w_kernel<<<2048, 256>>>(Wq, Wk, Wv);
    conv_x_kernel<<<2048, 256>>>(x);
    prep_kernel<<<1, 256>>>(v_bias, w_pos);
    conv_wo_kernel<<<768, 256>>>(Wo);

    gemm_mma<<<dim3(16, 16), 256>>>(0, nullptr, nullptr);   // fused QKV|QW

    uk_kernel<<<64, 256>>>(u_bias);
    suffix_kernel<<<4096, 256>>>();
    attn_kernel<<<dim3(8, 8, 2), 256, ATTN_SMEM>>>();

    conv_ao_kernel<<<2048, 256>>>();
    gemm_mma<<<dim3(6, 16), 256>>>(1, bo, out);             // out proj
}

// round 8
// speedup vs baseline: 1.7706x; 1.3380x over previous
#include <cuda_runtime.h>
#include <cuda_bf16.h>
#include <math.h>
#include <stdint.h>

#define NB 2
#define NL 1024
#define NH 8
#define ND 64
#define NDM 768
#define HD 512        /* NH*ND */
#define QLD 2048      /* g_qkv row stride: Q|K|V|QW */
#define KAUG_X 2304   /* 3*768 */
#define KAUG_O 1536   /* 3*512 */

// ------------------------- device scratch (no allocation) --------------------
static __device__ __align__(16) __nv_bfloat16 g_Aaug [NB*NL*KAUG_X];   // x hi|lo|hi
static __device__ __align__(16) __nv_bfloat16 g_Waug [2048*KAUG_X];    // Wq|Wk|Wv|W2 hi|hi|lo
static __device__ __align__(16) __nv_bfloat16 g_AOaug[NB*NL*KAUG_O];   // attn out hi|lo|hi
static __device__ __align__(16) __nv_bfloat16 g_WOaug[NDM*KAUG_O];     // Wo hi|hi|lo
static __device__ __align__(16) float g_W2 [HD*NDM];                   // folded Wq^T@wpos
static __device__ __align__(16) float g_qkv[NB*NL*QLD];                // K|QW fp32 regions used
// bf16 attention operands, [b][h][tok][d] (Q,K) and [b][h][d][tok] (V^T)
static __device__ __align__(16) __nv_bfloat16 g_qh[NB*NH*NL*ND];
static __device__ __align__(16) __nv_bfloat16 g_ql[NB*NH*NL*ND];
static __device__ __align__(16) __nv_bfloat16 g_kh[NB*NH*NL*ND];
static __device__ __align__(16) __nv_bfloat16 g_kl[NB*NH*NL*ND];
static __device__ __align__(16) __nv_bfloat16 g_vth[NB*NH*ND*NL];
static __device__ __align__(16) __nv_bfloat16 g_vtl[NB*NH*ND*NL];
static __device__ __align__(16) float g_uk [NB*NH*NL];
static __device__ __align__(16) float g_Su [NB*NH*NL*33];
static __device__ __align__(16) float g_Ss [NB*NH*NL*33];
static __device__ __align__(16) float g_VrU[NH*33];
static __device__ __align__(16) float g_VrS[NH*33];
static __device__ int   g_t[NL];

// ------------------------- conversion kernels --------------------------------
__device__ __forceinline__ void split_hl(float v, __nv_bfloat16& h, __nv_bfloat16& l) {
    h = __float2bfloat16(v);
    l = __float2bfloat16(v - __bfloat162float(h));
}

__global__ void conv_x_kernel(const float* __restrict__ x) {   // grid 2048
    int row = blockIdx.x;
    const float* src = x + (size_t)row * NDM;
    __nv_bfloat16* dst = g_Aaug + (size_t)row * KAUG_X;
    for (int c = threadIdx.x; c < NDM; c += 256) {
        __nv_bfloat16 h, l; split_hl(src[c], h, l);
        dst[c] = h; dst[NDM + c] = l; dst[2*NDM + c] = h;
    }
}

__global__ void fold_w2_kernel(const float* __restrict__ Wq,
                               const float* __restrict__ w_pos) { // grid 512
    __shared__ float wp[64];
    int hn = blockIdx.x, h = hn >> 6, n = hn & 63;
    if (threadIdx.x < 64) wp[threadIdx.x] = w_pos[h*4096 + threadIdx.x*64 + n];
    __syncthreads();
    for (int m = threadIdx.x; m < NDM; m += 256) {
        float s = 0.f;
#pragma unroll 16
        for (int d = 0; d < 64; d++)
            s += Wq[(size_t)(h*64 + d)*NDM + m] * wp[d];
        g_W2[(size_t)hn*NDM + m] = s;
    }
}

__global__ void conv_w_kernel(const float* __restrict__ Wq,
                              const float* __restrict__ Wk,
                              const float* __restrict__ Wv) {  // grid 2048
    int r = blockIdx.x;
    const float* src;
    if (r < 512)        src = Wq + (size_t)r * NDM;
    else if (r < 1024)  src = Wk + (size_t)(r-512) * NDM;
    else if (r < 1536)  src = Wv + (size_t)(r-1024) * NDM;
    else                src = g_W2 + (size_t)(r-1536) * NDM;
    __nv_bfloat16* dst = g_Waug + (size_t)r * KAUG_X;
    for (int c = threadIdx.x; c < NDM; c += 256) {
        __nv_bfloat16 h, l; split_hl(src[c], h, l);
        dst[c] = h; dst[NDM + c] = h; dst[2*NDM + c] = l;
    }
}

__global__ void conv_wo_kernel(const float* __restrict__ Wo) {  // grid 768
    int r = blockIdx.x;
    const float* src = Wo + (size_t)r * HD;
    __nv_bfloat16* dst = g_WOaug + (size_t)r * KAUG_O;
    for (int c = threadIdx.x; c < HD; c += 256) {
        __nv_bfloat16 h, l; split_hl(src[c], h, l);
        dst[c] = h; dst[HD + c] = h; dst[2*HD + c] = l;
    }
}

// ------------------------- mma.sync bf16 GEMM: C = A @ Bw^T ------------------
#define BM 128
#define BN 128
#define BK 32
#define GSTR 40

__device__ __forceinline__ void mma16816(float* c, const uint32_t* a, const uint32_t* b) {
    asm volatile(
        "mma.sync.aligned.m16n8k16.row.col.f32.bf16.bf16.f32 "
        "{%0,%1,%2,%3}, {%4,%5,%6,%7}, {%8,%9}, {%0,%1,%2,%3};"
        : "+f"(c[0]), "+f"(c[1]), "+f"(c[2]), "+f"(c[3])
        : "r"(a[0]), "r"(a[1]), "r"(a[2]), "r"(a[3]), "r"(b[0]), "r"(b[1]));
}

__global__ __launch_bounds__(256, 1)
void gemm_mma(int which, const float* __restrict__ bias, float* __restrict__ Cout)
{
    __shared__ __nv_bfloat16 sA[2][BM*GSTR];
    __shared__ __nv_bfloat16 sB[2][BN*GSTR];

    const int tid = threadIdx.x;
    const int wid = tid >> 5, lane = tid & 31;
    const int wm = wid >> 2, wn = wid & 3;
    const int m0 = blockIdx.y * BM, n0 = blockIdx.x * BN;

    const __nv_bfloat16 *A, *Bw;
    float* C; int Kaug, Ntot;
    if (which == 0) { A = g_Aaug;  Bw = g_Waug;  C = g_qkv; Kaug = KAUG_X; Ntot = QLD; }
    else            { A = g_AOaug; Bw = g_WOaug; C = Cout;  Kaug = KAUG_O; Ntot = NDM; }
    const int nk = Kaug / BK;

    const int ldrow = tid >> 2, ldg = tid & 3;

    auto prefetch = [&](int c) {
        int p = c & 1;
        {
            const __nv_bfloat16* Ab = A + (size_t)(m0 + ldrow) * Kaug + c*BK + ldg*8;
#pragma unroll
            for (int s = 0; s < 2; s++) {
                uint32_t dst = (uint32_t)__cvta_generic_to_shared(
                    &sA[p][(ldrow + s*64)*GSTR + ldg*8]);
                const void* src = Ab + (size_t)(s*64) * Kaug;
                asm volatile("cp.async.cg.shared.global [%0], [%1], 16;" :: "r"(dst), "l"(src));
            }
        }
        {
            const __nv_bfloat16* Bb = Bw + (size_t)(n0 + ldrow) * Kaug + c*BK + ldg*8;
#pragma unroll
            for (int s = 0; s < 2; s++) {
                uint32_t dst = (uint32_t)__cvta_generic_to_shared(
                    &sB[p][(ldrow + s*64)*GSTR + ldg*8]);
                const void* src = Bb + (size_t)(s*64) * Kaug;
                asm volatile("cp.async.cg.shared.global [%0], [%1], 16;" :: "r"(dst), "l"(src));
            }
        }
        asm volatile("cp.async.commit_group;" ::: "memory");
    };

    float acc[4][4][4];
#pragma unroll
    for (int i = 0; i < 4; i++)
#pragma unroll
        for (int j = 0; j < 4; j++)
#pragma unroll
            for (int r = 0; r < 4; r++) acc[i][j][r] = 0.f;

    prefetch(0);

    for (int c = 0; c < nk; c++) {
        int p = c & 1;
        if (c + 1 < nk) {
            prefetch(c + 1);
            asm volatile("cp.async.wait_group 1;" ::: "memory");
        } else {
            asm volatile("cp.async.wait_group 0;" ::: "memory");
        }
        __syncthreads();

        uint32_t aB = (uint32_t)__cvta_generic_to_shared(&sA[p][0]);
        uint32_t bB = (uint32_t)__cvta_generic_to_shared(&sB[p][0]);

#pragma unroll
        for (int ks = 0; ks < 2; ks++) {
            uint32_t a[4][4];
#pragma unroll
            for (int i = 0; i < 4; i++) {
                uint32_t addr = aB + (uint32_t)(
                    ((wm*64 + i*16 + (lane & 15))*GSTR + ((lane >> 4)*8) + ks*16) * 2);
                asm volatile("ldmatrix.sync.aligned.m8n8.x4.shared.b16 {%0,%1,%2,%3}, [%4];"
                    : "=r"(a[i][0]), "=r"(a[i][1]), "=r"(a[i][2]), "=r"(a[i][3]) : "r"(addr));
            }
            uint32_t b[4][2];
#pragma unroll
            for (int jp = 0; jp < 2; jp++) {
                uint32_t addr = bB + (uint32_t)(
                    ((wn*32 + jp*16 + (lane & 7) + ((lane >> 4) << 3))*GSTR
                     + (((lane >> 3) & 1) << 3) + ks*16) * 2);
                asm volatile("ldmatrix.sync.aligned.m8n8.x4.shared.b16 {%0,%1,%2,%3}, [%4];"
                    : "=r"(b[2*jp][0]), "=r"(b[2*jp][1]),
                      "=r"(b[2*jp+1][0]), "=r"(b[2*jp+1][1]) : "r"(addr));
            }
#pragma unroll
            for (int i = 0; i < 4; i++)
#pragma unroll
                for (int j = 0; j < 4; j++)
                    mma16816(acc[i][j], a[i], b[j]);
        }
        __syncthreads();
    }

    // epilogue
    if (which == 1) {
#pragma unroll
        for (int i = 0; i < 4; i++) {
            int r0 = m0 + wm*64 + i*16 + (lane >> 2);
#pragma unroll
            for (int j = 0; j < 4; j++) {
                int col = n0 + wn*32 + j*8 + (lane & 3)*2;
                float b0 = bias[col], b1 = bias[col+1];
                *(float2*)(C + (size_t)r0 * Ntot + col) =
                    make_float2(acc[i][j][0] + b0, acc[i][j][1] + b1);
                *(float2*)(C + (size_t)(r0 + 8) * Ntot + col) =
                    make_float2(acc[i][j][2] + b0, acc[i][j][3] + b1);
            }
        }
        return;
    }

    // which == 0: scatter into fp32 (K,QW regions) + bf16 attention operands
    auto emit = [&](int row, int col, float v0, float v1) {
        int reg = col >> 9;
        int bb = row >> 10, tok = row & 1023;
        int h = (col >> 6) & 7, d = col & 63;
        if (reg == 1 || reg == 3)
            *(float2*)(g_qkv + (size_t)row*QLD + col) = make_float2(v0, v1);
        if (reg == 3) return;
        __nv_bfloat16 h0, l0, h1, l1;
        split_hl(v0, h0, l0); split_hl(v1, h1, l1);
        if (reg == 2) {
            size_t vk = ((size_t)((bb*8+h)*64 + d))*1024 + tok;
            g_vth[vk] = h0; g_vtl[vk] = l0;
            g_vth[vk + 1024] = h1; g_vtl[vk + 1024] = l1;
            return;
        }
        size_t qk = ((size_t)((bb*8+h)*1024 + tok))*64 + d;
        if (reg == 0) {
            *(__nv_bfloat162*)(g_qh + qk) = __nv_bfloat162(h0, h1);
            *(__nv_bfloat162*)(g_ql + qk) = __nv_bfloat162(l0, l1);
        } else {
            *(__nv_bfloat162*)(g_kh + qk) = __nv_bfloat162(h0, h1);
            *(__nv_bfloat162*)(g_kl + qk) = __nv_bfloat162(l0, l1);
        }
    };
#pragma unroll
    for (int i = 0; i < 4; i++) {
        int r0 = m0 + wm*64 + i*16 + (lane >> 2);
#pragma unroll
        for (int j = 0; j < 4; j++) {
            int col = n0 + wn*32 + j*8 + (lane & 3)*2;
            emit(r0,     col, acc[i][j][0], acc[i][j][1]);
            emit(r0 + 8, col, acc[i][j][2], acc[i][j][3]);
        }
    }
}

// ---------------- uk[b,h,j] = sum_d u_bias[h,d] * k[b,j,h,d] -----------------
__global__ __launch_bounds__(256)
void uk_kernel(const float* __restrict__ u_bias)
{
    int idx = blockIdx.x*256 + threadIdx.x;       // 0..16383
    int bh = idx >> 10, j = idx & 1023;
    int b = bh >> 3, hh = bh & 7;
    const float* kr = g_qkv + (size_t)(b*NL + j)*QLD + 512 + hh*ND;
    const float* ub = u_bias + hh*ND;
    float s = 0.f;
#pragma unroll
    for (int d = 0; d < ND; d += 4) {
        float4 kv = *(const float4*)(kr + d);
        float4 uv = *(const float4*)(ub + d);
        s += kv.x*uv.x + kv.y*uv.y + kv.z*uv.z + kv.w*uv.w;
    }
    g_uk[idx] = s;
}

// ---------------- prep: grid 5 — blocks 0..3 t-table, block 4 vr --------------
__global__ void prep_kernel(const float* __restrict__ v_bias,
                            const float* __restrict__ w_pos)
{
    __shared__ float cw[32];
    __shared__ float vws[512];
    const int tid = threadIdx.x;
    if (tid < 32) {
        float pr = expf(logf((float)(NL+1) * 0.5f) / 32.f);
        cw[tid] = powf(pr, (float)(tid+1));
    }
    __syncthreads();
    if (blockIdx.x < 4) {
        int a = blockIdx.x*256 + tid;
        int t = 32;
        for (int f = 0; f < 32; f++)
            if ((float)a <= cw[f]) { t = f; break; }
        g_t[a] = t;
        return;
    }
    for (int idx = tid; idx < 512; idx += 256) {
        int hh = idx >> 6, n = idx & 63;
        float s = 0.f;
        for (int d = 0; d < 64; d++)
            s += v_bias[hh*64 + d] * w_pos[hh*4096 + d*64 + n];
        vws[idx] = s;
    }
    __syncthreads();
    if (tid < 16) {
        int hh = tid >> 1, half = tid & 1;
        float* dst = (half ? g_VrS : g_VrU) + hh*33;
        const float* src = vws + hh*64 + half*32;
        float run = 0.f;
        dst[32] = 0.f;
        for (int f = 31; f >= 0; f--) { run += src[f]; dst[f] = run; }
    }
}

// ---------------- suffix sums of qw rows (+vr folded), warp-per-row ----------
__global__ __launch_bounds__(256)
void suffix_kernel()
{
    int gw = blockIdx.x*8 + (threadIdx.x >> 5);
    int lane = threadIdx.x & 31;
    int half = gw & 1;
    int pair = gw >> 1;
    int h = pair & 7;
    int row = pair >> 3;
    int b = row >> 10, i = row & 1023;

    float v = g_qkv[(size_t)row*QLD + 1536 + h*64 + half*32 + lane];
#pragma unroll
    for (int o = 1; o < 32; o <<= 1) {
        float t = __shfl_down_sync(0xffffffffu, v, o);
        if (lane + o < 32) v += t;
    }
    const float* vr = (half ? g_VrS : g_VrU) + h*33;
    float* dst = (half ? g_Ss : g_Su) + (size_t)((b*NH + h)*NL + i)*33;
    dst[lane] = v + vr[lane];
    if (lane == 0) dst[32] = vr[32];
}

// ---------------- flash attention, HMMA, factored rel-pos bias ---------------
#define QSTR 72    /* Q/K smem row stride (bf16): 144B, 144%128=16 -> conflict-free */
#define VSTR 136   /* V^T smem row stride: 272B, %128=16 */
#define AOFF_QH 0
#define AOFF_QL (AOFF_QH + 128*QSTR*2)
#define AOFF_KH (AOFF_QL + 128*QSTR*2)
#define AOFF_KL (AOFF_KH + 128*QSTR*2)
#define AOFF_VH (AOFF_KL + 128*QSTR*2)
#define AOFF_VL (AOFF_VH + 64*VSTR*2)
#define AOFF_SU (AOFF_VL + 64*VSTR*2)
#define AOFF_SS (AOFF_SU + 128*33*4)
#define AOFF_UK (AOFF_SS + 128*33*4)
#define AOFF_TS (AOFF_UK + 1024*4)
#define ATTN_SMEM (AOFF_TS + 1024*4)

__global__ __launch_bounds__(256, 1)
void attn_kernel()
{
    extern __shared__ char smc[];
    __nv_bfloat16* sQh = (__nv_bfloat16*)(smc + AOFF_QH);
    __nv_bfloat16* sQl = (__nv_bfloat16*)(smc + AOFF_QL);
    __nv_bfloat16* sKh = (__nv_bfloat16*)(smc + AOFF_KH);
    __nv_bfloat16* sKl = (__nv_bfloat16*)(smc + AOFF_KL);
    __nv_bfloat16* sVh = (__nv_bfloat16*)(smc + AOFF_VH);
    __nv_bfloat16* sVl = (__nv_bfloat16*)(smc + AOFF_VL);
    float* SuS = (float*)(smc + AOFF_SU);
    float* SsS = (float*)(smc + AOFF_SS);
    float* uks = (float*)(smc + AOFF_UK);
    int*   ts  = (int*)(smc + AOFF_TS);

    const int tid = threadIdx.x;
    const int wid = tid >> 5, lane = tid & 31;
    const int it = blockIdx.x, hh = blockIdx.y, b = blockIdx.z;
    const int i0 = it * 128;
    const int bh = b*NH + hh;
    const float scale = 0.125f;

    const size_t qkbase = (size_t)(bh*NL) * ND;      // Q/K [tok][d]
    const size_t vtbase = (size_t)(bh*ND) * NL;      // V^T [d][tok]

    // prologue: Q tiles + tables
    for (int idx = tid; idx < 1024; idx += 256) {    // 128 rows x 8 chunks(16B)
        int row = idx >> 3, g = idx & 7;
        size_t src = qkbase + (size_t)(i0 + row)*ND + g*8;
        *(uint4*)(sQh + row*QSTR + g*8) = *(const uint4*)(g_qh + src);
        *(uint4*)(sQl + row*QSTR + g*8) = *(const uint4*)(g_ql + src);
    }
    for (int idx = tid; idx < 128*33; idx += 256) {
        SuS[idx] = g_Su[(size_t)(bh*NL + i0)*33 + idx];
        SsS[idx] = g_Ss[(size_t)(bh*NL + i0)*33 + idx];
    }
    for (int idx = tid; idx < NL; idx += 256) {
        uks[idx] = g_uk[bh*NL + idx];
        ts[idx]  = g_t[idx];
    }

    const int il0 = wid*16 + (lane >> 2);
    const int ig0 = i0 + il0, ig1 = ig0 + 8;

    float m0_ = -1e30f, m1_ = -1e30f, l0_ = 0.f, l1_ = 0.f;
    float oacc[8][4];
#pragma unroll
    for (int d = 0; d < 8; d++)
#pragma unroll
        for (int e = 0; e < 4; e++) oacc[d][e] = 0.f;

    for (int jc = 0; jc < 8; jc++) {
        const int j0 = jc * 128;
        __syncthreads();
        for (int idx = tid; idx < 1024; idx += 256) {
            int row = idx >> 3, g = idx & 7;
            size_t src = qkbase + (size_t)(j0 + row)*ND + g*8;
            *(uint4*)(sKh + row*QSTR + g*8) = *(const uint4*)(g_kh + src);
            *(uint4*)(sKl + row*QSTR + g*8) = *(const uint4*)(g_kl + src);
        }
        for (int idx = tid; idx < 1024; idx += 256) { // 64 d-rows x 16 chunks
            int d = idx >> 4, g = idx & 15;
            size_t src = vtbase + (size_t)d*NL + j0 + g*8;
            *(uint4*)(sVh + d*VSTR + g*8) = *(const uint4*)(g_vth + src);
            *(uint4*)(sVl + d*VSTR + g*8) = *(const uint4*)(g_vtl + src);
        }
        __syncthreads();

        // ---- S = Qh Kh^T + Ql Kh^T + Qh Kl^T ----
        float sacc[16][4];
#pragma unroll
        for (int jt = 0; jt < 16; jt++)
#pragma unroll
            for (int e = 0; e < 4; e++) sacc[jt][e] = 0.f;

        uint32_t aQbase = (uint32_t)__cvta_generic_to_shared(sQh);
        uint32_t aQlb   = (uint32_t)__cvta_generic_to_shared(sQl);
        uint32_t aKbase = (uint32_t)__cvta_generic_to_shared(sKh);
        uint32_t aKlb   = (uint32_t)__cvta_generic_to_shared(sKl);

#pragma unroll
        for (int ks = 0; ks < 4; ks++) {
            uint32_t aqh[4], aql[4];
            {
                uint32_t addr = aQbase + (uint32_t)(
                    ((wid*16 + (lane & 15))*QSTR + (lane >> 4)*8 + ks*16) * 2);
                asm volatile("ldmatrix.sync.aligned.m8n8.x4.shared.b16 {%0,%1,%2,%3}, [%4];"
                    : "=r"(aqh[0]), "=r"(aqh[1]), "=r"(aqh[2]), "=r"(aqh[3]) : "r"(addr));
                addr = aQlb + (uint32_t)(
                    ((wid*16 + (lane & 15))*QSTR + (lane >> 4)*8 + ks*16) * 2);
                asm volatile("ldmatrix.sync.aligned.m8n8.x4.shared.b16 {%0,%1,%2,%3}, [%4];"
                    : "=r"(aql[0]), "=r"(aql[1]), "=r"(aql[2]), "=r"(aql[3]) : "r"(addr));
            }
            uint32_t bk[16][2];
#pragma unroll
            for (int jt2 = 0; jt2 < 8; jt2++) {
                uint32_t addr = aKbase + (uint32_t)(
                    ((jt2*16 + (lane & 7) + ((lane >> 4) << 3))*QSTR
                     + (((lane >> 3) & 1) << 3) + ks*16) * 2);
                asm volatile("ldmatrix.sync.aligned.m8n8.x4.shared.b16 {%0,%1,%2,%3}, [%4];"
                    : "=r"(bk[2*jt2][0]), "=r"(bk[2*jt2][1]),
                      "=r"(bk[2*jt2+1][0]), "=r"(bk[2*jt2+1][1]) : "r"(addr));
            }
#pragma unroll
            for (int jt = 0; jt < 16; jt++) mma16816(sacc[jt], aqh, bk[jt]);
#pragma unroll
            for (int jt = 0; jt < 16; jt++) mma16816(sacc[jt], aql, bk[jt]);
#pragma unroll
            for (int jt2 = 0; jt2 < 8; jt2++) {
                uint32_t addr = aKlb + (uint32_t)(
                    ((jt2*16 + (lane & 7) + ((lane >> 4) << 3))*QSTR
                     + (((lane >> 3) & 1) << 3) + ks*16) * 2);
                asm volatile("ldmatrix.sync.aligned.m8n8.x4.shared.b16 {%0,%1,%2,%3}, [%4];"
                    : "=r"(bk[2*jt2][0]), "=r"(bk[2*jt2][1]),
                      "=r"(bk[2*jt2+1][0]), "=r"(bk[2*jt2+1][1]) : "r"(addr));
            }
#pragma unroll
            for (int jt = 0; jt < 16; jt++) mma16816(sacc[jt], aqh, bk[jt]);
        }

        // ---- bias + online softmax (rows fully in-warp) ----
        float mx0 = -1e30f, mx1 = -1e30f;
#pragma unroll
        for (int jt = 0; jt < 16; jt++) {
            int jbase = j0 + jt*8 + (lane & 3)*2;
#pragma unroll
            for (int c = 0; c < 2; c++) {
                int jg = jbase + c;
                float ukv = uks[jg];
                {
                    int dd = jg - ig0;
                    int a = dd < 0 ? -dd : dd;
                    int t = ts[a];
                    float ss = SsS[il0*33 + t];
                    float bias = SuS[il0*33 + t] + (dd > 0 ? ss : (dd < 0 ? -ss : 0.f)) + ukv;
                    float v = (sacc[jt][c] + bias) * scale;
                    sacc[jt][c] = v; mx0 = fmaxf(mx0, v);
                }
                {
                    int dd = jg - ig1;
                    int a = dd < 0 ? -dd : dd;
                    int t = ts[a];
                    float ss = SsS[(il0+8)*33 + t];
                    float bias = SuS[(il0+8)*33 + t] + (dd > 0 ? ss : (dd < 0 ? -ss : 0.f)) + ukv;
                    float v = (sacc[jt][2+c] + bias) * scale;
                    sacc[jt][2+c] = v; mx1 = fmaxf(mx1, v);
                }
            }
        }
        mx0 = fmaxf(mx0, __shfl_xor_sync(0xffffffffu, mx0, 1));
        mx0 = fmaxf(mx0, __shfl_xor_sync(0xffffffffu, mx0, 2));
        mx1 = fmaxf(mx1, __shfl_xor_sync(0xffffffffu, mx1, 1));
        mx1 = fmaxf(mx1, __shfl_xor_sync(0xffffffffu, mx1, 2));

        float mn0 = fmaxf(m0_, mx0), mn1 = fmaxf(m1_, mx1);
        float al0 = __expf(m0_ - mn0), al1 = __expf(m1_ - mn1);
        float rs0 = 0.f, rs1 = 0.f;
#pragma unroll
        for (int jt = 0; jt < 16; jt++) {
            float p0 = __expf(sacc[jt][0] - mn0);
            float p1 = __expf(sacc[jt][1] - mn0);
            float p2 = __expf(sacc[jt][2] - mn1);
            float p3 = __expf(sacc[jt][3] - mn1);
            sacc[jt][0] = p0; sacc[jt][1] = p1; sacc[jt][2] = p2; sacc[jt][3] = p3;
            rs0 += p0 + p1; rs1 += p2 + p3;
        }
        rs0 += __shfl_xor_sync(0xffffffffu, rs0, 1);
        rs0 += __shfl_xor_sync(0xffffffffu, rs0, 2);
        rs1 += __shfl_xor_sync(0xffffffffu, rs1, 1);
        rs1 += __shfl_xor_sync(0xffffffffu, rs1, 2);
        l0_ = l0_*al0 + rs0; l1_ = l1_*al1 + rs1;
        m0_ = mn0; m1_ = mn1;
#pragma unroll
        for (int d = 0; d < 8; d++) {
            oacc[d][0] *= al0; oacc[d][1] *= al0;
            oacc[d][2] *= al1; oacc[d][3] *= al1;
        }

        // ---- O += Ph Vh + Pl Vh + Ph Vl ----
        // A-fragment from accumulator: a0=(r,k), a1=(r+8,k), a2=(r,k+8), a3=(r+8,k+8)
        // = [sacc[2g][0:2], sacc[2g][2:4], sacc[2g+1][0:2], sacc[2g+1][2:4]] — NO reorder.
        uint32_t vHb = (uint32_t)__cvta_generic_to_shared(sVh);
        uint32_t vLb = (uint32_t)__cvta_generic_to_shared(sVl);
#pragma unroll
        for (int g = 0; g < 8; g++) {
            uint32_t aph[4], apl[4];
#pragma unroll
            for (int q = 0; q < 4; q++) {
                int jt = 2*g + (q >> 1);
                int eb = (q & 1) * 2;
                float p0 = sacc[jt][eb], p1 = sacc[jt][eb+1];
                __nv_bfloat16 h0 = __float2bfloat16(p0);
                __nv_bfloat16 h1 = __float2bfloat16(p1);
                __nv_bfloat162 hp(h0, h1);
                aph[q] = *(uint32_t*)&hp;
                __nv_bfloat162 lp(__float2bfloat16(p0 - __bfloat162float(h0)),
                                  __float2bfloat16(p1 - __bfloat162float(h1)));
                apl[q] = *(uint32_t*)&lp;
            }

            uint32_t bv[8][2];
#pragma unroll
            for (int dt2 = 0; dt2 < 4; dt2++) {
                uint32_t addr = vHb + (uint32_t)(
                    ((dt2*16 + (lane & 7) + ((lane >> 4) << 3))*VSTR
                     + (((lane >> 3) & 1) << 3) + g*16) * 2);
                asm volatile("ldmatrix.sync.aligned.m8n8.x4.shared.b16 {%0,%1,%2,%3}, [%4];"
                    : "=r"(bv[2*dt2][0]), "=r"(bv[2*dt2][1]),
                      "=r"(bv[2*dt2+1][0]), "=r"(bv[2*dt2+1][1]) : "r"(addr));
            }
#pragma unroll
            for (int dt = 0; dt < 8; dt++) mma16816(oacc[dt], aph, bv[dt]);
#pragma unroll
            for (int dt = 0; dt < 8; dt++) mma16816(oacc[dt], apl, bv[dt]);
#pragma unroll
            for (int dt2 = 0; dt2 < 4; dt2++) {
                uint32_t addr = vLb + (uint32_t)(
                    ((dt2*16 + (lane & 7) + ((lane >> 4) << 3))*VSTR
                     + (((lane >> 3) & 1) << 3) + g*16) * 2);
                asm volatile("ldmatrix.sync.aligned.m8n8.x4.shared.b16 {%0,%1,%2,%3}, [%4];"
                    : "=r"(bv[2*dt2][0]), "=r"(bv[2*dt2][1]),
                      "=r"(bv[2*dt2+1][0]), "=r"(bv[2*dt2+1][1]) : "r"(addr));
            }
#pragma unroll
            for (int dt = 0; dt < 8; dt++) mma16816(oacc[dt], aph, bv[dt]);
        }
    }

    // ---- epilogue: normalize, write bf16 hi|lo|hi aug directly ----
    float inv0 = 1.f / l0_, inv1 = 1.f / l1_;
    int row0 = b*NL + ig0;   // global AO row for slot 0
    int colb = hh*64 + (lane & 3)*2;
#pragma unroll
    for (int dt = 0; dt < 8; dt++) {
        int col = colb + dt*8;
        float o0 = oacc[dt][0]*inv0, o1 = oacc[dt][1]*inv0;
        float o2 = oacc[dt][2]*inv1, o3 = oacc[dt][3]*inv1;
        __nv_bfloat16 h0, l0v, h1, l1v, h2, l2v, h3, l3v;
        split_hl(o0, h0, l0v); split_hl(o1, h1, l1v);
        split_hl(o2, h2, l2v); split_hl(o3, h3, l3v);
        __nv_bfloat16* base0 = g_AOaug + (size_t)row0 * KAUG_O + col;
        __nv_bfloat16* base1 = g_AOaug + (size_t)(row0 + 8) * KAUG_O + col;
        *(__nv_bfloat162*)(base0)        = __nv_bfloat162(h0, h1);
        *(__nv_bfloat162*)(base0 + 512)  = __nv_bfloat162(l0v, l1v);
        *(__nv_bfloat162*)(base0 + 1024) = __nv_bfloat162(h0, h1);
        *(__nv_bfloat162*)(base1)        = __nv_bfloat162(h2, h3);
        *(__nv_bfloat162*)(base1 + 512)  = __nv_bfloat162(l2v, l3v);
        *(__nv_bfloat162*)(base1 + 1024) = __nv_bfloat162(h2, h3);
    }
}

// ----------------------------------------------------------------------------
extern "C" void kernel_launch(void* const* d_in, const int* in_sizes, int n_in,
                              void* d_out, int out_size)
{
    const float* x      = (const float*)d_in[0];
    const float* Wq     = (const float*)d_in[1];
    const float* Wk     = (const float*)d_in[2];
    const float* Wv     = (const float*)d_in[3];
    const float* Wo     = (const float*)d_in[4];
    const float* bo     = (const float*)d_in[5];
    const float* u_bias = (const float*)d_in[6];
    const float* v_bias = (const float*)d_in[7];
    const float* w_pos  = (const float*)d_in[8];
    float* out = (float*)d_out;

    cudaFuncSetAttribute(attn_kernel,
                         cudaFuncAttributeMaxDynamicSharedMemorySize, ATTN_SMEM);

    fold_w2_kernel<<<512, 256>>>(Wq, w_pos);
    conv_w_kernel<<<2048, 256>>>(Wq, Wk, Wv);
    conv_x_kernel<<<2048, 256>>>(x);
    prep_kernel<<<5, 256>>>(v_bias, w_pos);
    conv_wo_kernel<<<768, 256>>>(Wo);

    gemm_mma<<<dim3(16, 16), 256>>>(0, nullptr, nullptr);   // fused QKV|QW

    uk_kernel<<<64, 256>>>(u_bias);
    suffix_kernel<<<4096, 256>>>();
    attn_kernel<<<dim3(8, 8, 2), 256, ATTN_SMEM>>>();

    gemm_mma<<<dim3(6, 16), 256>>>(1, bo, out);             // out proj
}

// round 10
// speedup vs baseline: 1.8686x; 1.0553x over previous
#include <cuda_runtime.h>
#include <cuda_bf16.h>
#include <cuda_fp16.h>
#include <math.h>
#include <stdint.h>

#define NB 2
#define NL 1024
#define NH 8
#define ND 64
#define NDM 768
#define HD 512        /* NH*ND */
#define QLD 2048      /* g_qkv row stride: Q|K|V|QW */
#define KAUG_X 2304   /* 3*768 */
#define KAUG_O 1536   /* 3*512 */

// ------------------------- device scratch (no allocation) --------------------
static __device__ __align__(16) __nv_bfloat16 g_Aaug [NB*NL*KAUG_X];   // x hi|lo|hi
static __device__ __align__(16) __nv_bfloat16 g_Waug [2048*KAUG_X];    // Wq|Wk|Wv|W2 hi|hi|lo
static __device__ __align__(16) __nv_bfloat16 g_AOaug[NB*NL*KAUG_O];   // attn out hi|lo|hi
static __device__ __align__(16) __nv_bfloat16 g_WOaug[NDM*KAUG_O];     // Wo hi|hi|lo
static __device__ __align__(16) float g_W2 [HD*NDM];                   // folded Wq^T@wpos
static __device__ __align__(16) float g_qkv[NB*NL*QLD];                // K|QW fp32 regions used
// fp16 attention operands, [b][h][tok][d] (Q,K) and [b][h][d][tok] (V^T)
static __device__ __align__(16) __half g_qh[NB*NH*NL*ND];
static __device__ __align__(16) __half g_ql[NB*NH*NL*ND];
static __device__ __align__(16) __half g_kh[NB*NH*NL*ND];
static __device__ __align__(16) __half g_vth[NB*NH*ND*NL];
static __device__ __align__(16) __half g_vtl[NB*NH*ND*NL];
static __device__ __align__(16) float g_uk [NB*NH*NL];
static __device__ __align__(16) float g_Su [NB*NH*NL*33];
static __device__ __align__(16) float g_Ss [NB*NH*NL*33];
static __device__ __align__(16) float g_VrU[NH*33];
static __device__ __align__(16) float g_VrS[NH*33];
static __device__ int   g_t[NL];

// ------------------------- conversion kernels --------------------------------
__device__ __forceinline__ void split_hl(float v, __nv_bfloat16& h, __nv_bfloat16& l) {
    h = __float2bfloat16(v);
    l = __float2bfloat16(v - __bfloat162float(h));
}
__device__ __forceinline__ void split_hl16(float v, __half& h, __half& l) {
    h = __float2half(v);
    l = __float2half(v - __half2float(h));
}

__global__ void conv_x_kernel(const float* __restrict__ x) {   // grid 2048
    int row = blockIdx.x;
    const float* src = x + (size_t)row * NDM;
    __nv_bfloat16* dst = g_Aaug + (size_t)row * KAUG_X;
    for (int c = threadIdx.x; c < NDM; c += 256) {
        __nv_bfloat16 h, l; split_hl(src[c], h, l);
        dst[c] = h; dst[NDM + c] = l; dst[2*NDM + c] = h;
    }
}

__global__ void fold_w2_kernel(const float* __restrict__ Wq,
                               const float* __restrict__ w_pos) { // grid 512
    __shared__ float wp[64];
    int hn = blockIdx.x, h = hn >> 6, n = hn & 63;
    if (threadIdx.x < 64) wp[threadIdx.x] = w_pos[h*4096 + threadIdx.x*64 + n];
    __syncthreads();
    for (int m = threadIdx.x; m < NDM; m += 256) {
        float s = 0.f;
#pragma unroll 16
        for (int d = 0; d < 64; d++)
            s += Wq[(size_t)(h*64 + d)*NDM + m] * wp[d];
        g_W2[(size_t)hn*NDM + m] = s;
    }
}

__global__ void conv_w_kernel(const float* __restrict__ Wq,
                              const float* __restrict__ Wk,
                              const float* __restrict__ Wv) {  // grid 2048
    int r = blockIdx.x;
    const float* src;
    if (r < 512)        src = Wq + (size_t)r * NDM;
    else if (r < 1024)  src = Wk + (size_t)(r-512) * NDM;
    else if (r < 1536)  src = Wv + (size_t)(r-1024) * NDM;
    else                src = g_W2 + (size_t)(r-1536) * NDM;
    __nv_bfloat16* dst = g_Waug + (size_t)r * KAUG_X;
    for (int c = threadIdx.x; c < NDM; c += 256) {
        __nv_bfloat16 h, l; split_hl(src[c], h, l);
        dst[c] = h; dst[NDM + c] = h; dst[2*NDM + c] = l;
    }
}

__global__ void conv_wo_kernel(const float* __restrict__ Wo) {  // grid 768
    int r = blockIdx.x;
    const float* src = Wo + (size_t)r * HD;
    __nv_bfloat16* dst = g_WOaug + (size_t)r * KAUG_O;
    for (int c = threadIdx.x; c < HD; c += 256) {
        __nv_bfloat16 h, l; split_hl(src[c], h, l);
        dst[c] = h; dst[HD + c] = h; dst[2*HD + c] = l;
    }
}

// ------------------------- mma.sync GEMM: C = A @ Bw^T -----------------------
#define BM 128
#define BN 128
#define BK 32
#define GSTR 40

__device__ __forceinline__ void mma16816(float* c, const uint32_t* a, const uint32_t* b) {
    asm volatile(
        "mma.sync.aligned.m16n8k16.row.col.f32.bf16.bf16.f32 "
        "{%0,%1,%2,%3}, {%4,%5,%6,%7}, {%8,%9}, {%0,%1,%2,%3};"
        : "+f"(c[0]), "+f"(c[1]), "+f"(c[2]), "+f"(c[3])
        : "r"(a[0]), "r"(a[1]), "r"(a[2]), "r"(a[3]), "r"(b[0]), "r"(b[1]));
}
__device__ __forceinline__ void mma16816h(float* c, const uint32_t* a, const uint32_t* b) {
    asm volatile(
        "mma.sync.aligned.m16n8k16.row.col.f32.f16.f16.f32 "
        "{%0,%1,%2,%3}, {%4,%5,%6,%7}, {%8,%9}, {%0,%1,%2,%3};"
        : "+f"(c[0]), "+f"(c[1]), "+f"(c[2]), "+f"(c[3])
        : "r"(a[0]), "r"(a[1]), "r"(a[2]), "r"(a[3]), "r"(b[0]), "r"(b[1]));
}

__global__ __launch_bounds__(256, 1)
void gemm_mma(int which, const float* __restrict__ bias, float* __restrict__ Cout)
{
    __shared__ __nv_bfloat16 sA[2][BM*GSTR];
    __shared__ __nv_bfloat16 sB[2][BN*GSTR];

    const int tid = threadIdx.x;
    const int wid = tid >> 5, lane = tid & 31;
    const int wm = wid >> 2, wn = wid & 3;
    const int m0 = blockIdx.y * BM, n0 = blockIdx.x * BN;

    const __nv_bfloat16 *A, *Bw;
    float* C; int Kaug, Ntot;
    if (which == 0) { A = g_Aaug;  Bw = g_Waug;  C = g_qkv; Kaug = KAUG_X; Ntot = QLD; }
    else            { A = g_AOaug; Bw = g_WOaug; C = Cout;  Kaug = KAUG_O; Ntot = NDM; }
    const int nk = Kaug / BK;

    const int ldrow = tid >> 2, ldg = tid & 3;

    auto prefetch = [&](int c) {
        int p = c & 1;
        {
            const __nv_bfloat16* Ab = A + (size_t)(m0 + ldrow) * Kaug + c*BK + ldg*8;
#pragma unroll
            for (int s = 0; s < 2; s++) {
                uint32_t dst = (uint32_t)__cvta_generic_to_shared(
                    &sA[p][(ldrow + s*64)*GSTR + ldg*8]);
                const void* src = Ab + (size_t)(s*64) * Kaug;
                asm volatile("cp.async.cg.shared.global [%0], [%1], 16;" :: "r"(dst), "l"(src));
            }
        }
        {
            const __nv_bfloat16* Bb = Bw + (size_t)(n0 + ldrow) * Kaug + c*BK + ldg*8;
#pragma unroll
            for (int s = 0; s < 2; s++) {
                uint32_t dst = (uint32_t)__cvta_generic_to_shared(
                    &sB[p][(ldrow + s*64)*GSTR + ldg*8]);
                const void* src = Bb + (size_t)(s*64) * Kaug;
                asm volatile("cp.async.cg.shared.global [%0], [%1], 16;" :: "r"(dst), "l"(src));
            }
        }
        asm volatile("cp.async.commit_group;" ::: "memory");
    };

    float acc[4][4][4];
#pragma unroll
    for (int i = 0; i < 4; i++)
#pragma unroll
        for (int j = 0; j < 4; j++)
#pragma unroll
            for (int r = 0; r < 4; r++) acc[i][j][r] = 0.f;

    prefetch(0);

    for (int c = 0; c < nk; c++) {
        int p = c & 1;
        if (c + 1 < nk) {
            prefetch(c + 1);
            asm volatile("cp.async.wait_group 1;" ::: "memory");
        } else {
            asm volatile("cp.async.wait_group 0;" ::: "memory");
        }
        __syncthreads();

        uint32_t aB = (uint32_t)__cvta_generic_to_shared(&sA[p][0]);
        uint32_t bB = (uint32_t)__cvta_generic_to_shared(&sB[p][0]);

#pragma unroll
        for (int ks = 0; ks < 2; ks++) {
            uint32_t a[4][4];
#pragma unroll
            for (int i = 0; i < 4; i++) {
                uint32_t addr = aB + (uint32_t)(
                    ((wm*64 + i*16 + (lane & 15))*GSTR + ((lane >> 4)*8) + ks*16) * 2);
                asm volatile("ldmatrix.sync.aligned.m8n8.x4.shared.b16 {%0,%1,%2,%3}, [%4];"
                    : "=r"(a[i][0]), "=r"(a[i][1]), "=r"(a[i][2]), "=r"(a[i][3]) : "r"(addr));
            }
            uint32_t b[4][2];
#pragma unroll
            for (int jp = 0; jp < 2; jp++) {
                uint32_t addr = bB + (uint32_t)(
                    ((wn*32 + jp*16 + (lane & 7) + ((lane >> 4) << 3))*GSTR
                     + (((lane >> 3) & 1) << 3) + ks*16) * 2);
                asm volatile("ldmatrix.sync.aligned.m8n8.x4.shared.b16 {%0,%1,%2,%3}, [%4];"
                    : "=r"(b[2*jp][0]), "=r"(b[2*jp][1]),
                      "=r"(b[2*jp+1][0]), "=r"(b[2*jp+1][1]) : "r"(addr));
            }
#pragma unroll
            for (int i = 0; i < 4; i++)
#pragma unroll
                for (int j = 0; j < 4; j++)
                    mma16816(acc[i][j], a[i], b[j]);
        }
        __syncthreads();
    }

    // epilogue
    if (which == 1) {
#pragma unroll
        for (int i = 0; i < 4; i++) {
            int r0 = m0 + wm*64 + i*16 + (lane >> 2);
#pragma unroll
            for (int j = 0; j < 4; j++) {
                int col = n0 + wn*32 + j*8 + (lane & 3)*2;
                float b0 = bias[col], b1 = bias[col+1];
                *(float2*)(C + (size_t)r0 * Ntot + col) =
                    make_float2(acc[i][j][0] + b0, acc[i][j][1] + b1);
                *(float2*)(C + (size_t)(r0 + 8) * Ntot + col) =
                    make_float2(acc[i][j][2] + b0, acc[i][j][3] + b1);
            }
        }
        return;
    }

    // which == 0: scatter into fp32 (K,QW regions) + fp16 attention operands
    auto emit = [&](int row, int col, float v0, float v1) {
        int reg = col >> 9;
        int bb = row >> 10, tok = row & 1023;
        int h = (col >> 6) & 7, d = col & 63;
        if (reg == 1 || reg == 3)
            *(float2*)(g_qkv + (size_t)row*QLD + col) = make_float2(v0, v1);
        if (reg == 3) return;
        __half h0, l0, h1, l1;
        split_hl16(v0, h0, l0); split_hl16(v1, h1, l1);
        if (reg == 2) {
            size_t vk = ((size_t)((bb*8+h)*64 + d))*1024 + tok;
            g_vth[vk] = h0; g_vtl[vk] = l0;
            g_vth[vk + 1024] = h1; g_vtl[vk + 1024] = l1;
            return;
        }
        size_t qk = ((size_t)((bb*8+h)*1024 + tok))*64 + d;
        if (reg == 0) {
            *(__half2*)(g_qh + qk) = __half2(h0, h1);
            *(__half2*)(g_ql + qk) = __half2(l0, l1);
        } else {
            *(__half2*)(g_kh + qk) = __half2(h0, h1);
        }
    };
#pragma unroll
    for (int i = 0; i < 4; i++) {
        int r0 = m0 + wm*64 + i*16 + (lane >> 2);
#pragma unroll
        for (int j = 0; j < 4; j++) {
            int col = n0 + wn*32 + j*8 + (lane & 3)*2;
            emit(r0,     col, acc[i][j][0], acc[i][j][1]);
            emit(r0 + 8, col, acc[i][j][2], acc[i][j][3]);
        }
    }
}

// ---------------- prep: blocks 0..3 t-table; blocks 4..11 vr (per head) ------
__global__ void prep_kernel(const float* __restrict__ v_bias,
                            const float* __restrict__ w_pos)
{
    const int tid = threadIdx.x;
    if (blockIdx.x < 4) {
        __shared__ float cw[32];
        if (tid < 32) {
            float pr = expf(logf((float)(NL+1) * 0.5f) / 32.f);
            cw[tid] = powf(pr, (float)(tid+1));
        }
        __syncthreads();
        int a = blockIdx.x*256 + tid;
        int t = 32;
        for (int f = 0; f < 32; f++)
            if ((float)a <= cw[f]) { t = f; break; }
        g_t[a] = t;
        return;
    }
    int hh = blockIdx.x - 4;
    __shared__ float vws[64];
    if (tid < 64) {
        int n = tid;
        float s = 0.f;
        for (int d = 0; d < 64; d++)
            s += v_bias[hh*64 + d] * w_pos[hh*4096 + d*64 + n];
        vws[n] = s;
    }
    __syncthreads();
    if (tid < 2) {
        int half = tid;
        float* dst = (half ? g_VrS : g_VrU) + hh*33;
        const float* src = vws + half*32;
        float run = 0.f;
        dst[32] = 0.f;
        for (int f = 31; f >= 0; f--) { run += src[f]; dst[f] = run; }
    }
}

// -------- merged: suffix sums of qw rows (+vr) AND uk dot products -----------
__global__ __launch_bounds__(256)
void uksuf_kernel(const float* __restrict__ u_bias)
{
    if (blockIdx.x < 4096) {
        int gw = blockIdx.x*8 + (threadIdx.x >> 5);
        int lane = threadIdx.x & 31;
        int half = gw & 1;
        int pair = gw >> 1;
        int h = pair & 7;
        int row = pair >> 3;
        int b = row >> 10, i = row & 1023;

        float v = g_qkv[(size_t)row*QLD + 1536 + h*64 + half*32 + lane];
#pragma unroll
        for (int o = 1; o < 32; o <<= 1) {
            float t = __shfl_down_sync(0xffffffffu, v, o);
            if (lane + o < 32) v += t;
        }
        const float* vr = (half ? g_VrS : g_VrU) + h*33;
        float* dst = (half ? g_Ss : g_Su) + (size_t)((b*NH + h)*NL + i)*33;
        dst[lane] = v + vr[lane];
        if (lane == 0) dst[32] = vr[32];
        return;
    }
    int idx = (blockIdx.x - 4096)*256 + threadIdx.x;   // 0..16383
    int bh = idx >> 10, j = idx & 1023;
    int b = bh >> 3, hh = bh & 7;
    const float* kr = g_qkv + (size_t)(b*NL + j)*QLD + 512 + hh*ND;
    const float* ub = u_bias + hh*ND;
    float s = 0.f;
#pragma unroll
    for (int d = 0; d < ND; d += 4) {
        float4 kv = *(const float4*)(kr + d);
        float4 uv = *(const float4*)(ub + d);
        s += kv.x*uv.x + kv.y*uv.y + kv.z*uv.z + kv.w*uv.w;
    }
    g_uk[idx] = s;
}

// ---------------- flash attention, fp16 HMMA, factored rel-pos bias ----------
#define QSTR 72    /* Q/K smem row stride (fp16): 144B, 144%128=16 -> conflict-free */
#define VSTR 136   /* V^T smem row stride: 272B, %128=16 */
#define AOFF_QH 0
#define AOFF_QL (AOFF_QH + 128*QSTR*2)
#define AOFF_KH (AOFF_QL + 128*QSTR*2)
#define AOFF_VH (AOFF_KH + 128*QSTR*2)
#define AOFF_VL (AOFF_VH + 64*VSTR*2)
#define AOFF_SU (AOFF_VL + 64*VSTR*2)
#define AOFF_SS (AOFF_SU + 128*33*4)
#define AOFF_UK (AOFF_SS + 128*33*4)
#define AOFF_TS (AOFF_UK + 1024*4)
#define ATTN_SMEM (AOFF_TS + 1024*4)

__global__ __launch_bounds__(256, 1)
void attn_kernel()
{
    extern __shared__ char smc[];
    __half* sQh = (__half*)(smc + AOFF_QH);
    __half* sQl = (__half*)(smc + AOFF_QL);
    __half* sKh = (__half*)(smc + AOFF_KH);
    __half* sVh = (__half*)(smc + AOFF_VH);
    __half* sVl = (__half*)(smc + AOFF_VL);
    float* SuS = (float*)(smc + AOFF_SU);
    float* SsS = (float*)(smc + AOFF_SS);
    float* uks = (float*)(smc + AOFF_UK);
    int*   ts  = (int*)(smc + AOFF_TS);

    const int tid = threadIdx.x;
    const int wid = tid >> 5, lane = tid & 31;
    const int it = blockIdx.x, hh = blockIdx.y, b = blockIdx.z;
    const int i0 = it * 128;
    const int bh = b*NH + hh;
    const float scale = 0.125f;

    const size_t qkbase = (size_t)(bh*NL) * ND;      // Q/K [tok][d]
    const size_t vtbase = (size_t)(bh*ND) * NL;      // V^T [d][tok]

    // prologue: Q tiles + tables
    for (int idx = tid; idx < 1024; idx += 256) {    // 128 rows x 8 chunks(16B)
        int row = idx >> 3, g = idx & 7;
        size_t src = qkbase + (size_t)(i0 + row)*ND + g*8;
        *(uint4*)(sQh + row*QSTR + g*8) = *(const uint4*)(g_qh + src);
        *(uint4*)(sQl + row*QSTR + g*8) = *(const uint4*)(g_ql + src);
    }
    for (int idx = tid; idx < 128*33; idx += 256) {
        SuS[idx] = g_Su[(size_t)(bh*NL + i0)*33 + idx];
        SsS[idx] = g_Ss[(size_t)(bh*NL + i0)*33 + idx];
    }
    for (int idx = tid; idx < NL; idx += 256) {
        uks[idx] = g_uk[bh*NL + idx];
        ts[idx]  = g_t[idx];
    }

    const int il0 = wid*16 + (lane >> 2);
    const int ig0 = i0 + il0, ig1 = ig0 + 8;

    float m0_ = -1e30f, m1_ = -1e30f, l0_ = 0.f, l1_ = 0.f;
    float oacc[8][4];
#pragma unroll
    for (int d = 0; d < 8; d++)
#pragma unroll
        for (int e = 0; e < 4; e++) oacc[d][e] = 0.f;

    for (int jc = 0; jc < 8; jc++) {
        const int j0 = jc * 128;
        __syncthreads();
        for (int idx = tid; idx < 1024; idx += 256) {
            int row = idx >> 3, g = idx & 7;
            size_t src = qkbase + (size_t)(j0 + row)*ND + g*8;
            *(uint4*)(sKh + row*QSTR + g*8) = *(const uint4*)(g_kh + src);
        }
        for (int idx = tid; idx < 1024; idx += 256) { // 64 d-rows x 16 chunks
            int d = idx >> 4, g = idx & 15;
            size_t src = vtbase + (size_t)d*NL + j0 + g*8;
            *(uint4*)(sVh + d*VSTR + g*8) = *(const uint4*)(g_vth + src);
            *(uint4*)(sVl + d*VSTR + g*8) = *(const uint4*)(g_vtl + src);
        }
        __syncthreads();

        // ---- S = (Qh + Ql) @ Kh^T  (exact Q, fp16-rounded K) ----
        float sacc[16][4];
#pragma unroll
        for (int jt = 0; jt < 16; jt++)
#pragma unroll
            for (int e = 0; e < 4; e++) sacc[jt][e] = 0.f;

        uint32_t aQbase = (uint32_t)__cvta_generic_to_shared(sQh);
        uint32_t aQlb   = (uint32_t)__cvta_generic_to_shared(sQl);
        uint32_t aKbase = (uint32_t)__cvta_generic_to_shared(sKh);

#pragma unroll
        for (int ks = 0; ks < 4; ks++) {
            uint32_t aqh[4], aql[4];
            {
                uint32_t addr = aQbase + (uint32_t)(
                    ((wid*16 + (lane & 15))*QSTR + (lane >> 4)*8 + ks*16) * 2);
                asm volatile("ldmatrix.sync.aligned.m8n8.x4.shared.b16 {%0,%1,%2,%3}, [%4];"
                    : "=r"(aqh[0]), "=r"(aqh[1]), "=r"(aqh[2]), "=r"(aqh[3]) : "r"(addr));
                addr = aQlb + (uint32_t)(
                    ((wid*16 + (lane & 15))*QSTR + (lane >> 4)*8 + ks*16) * 2);
                asm volatile("ldmatrix.sync.aligned.m8n8.x4.shared.b16 {%0,%1,%2,%3}, [%4];"
                    : "=r"(aql[0]), "=r"(aql[1]), "=r"(aql[2]), "=r"(aql[3]) : "r"(addr));
            }
            uint32_t bk[16][2];
#pragma unroll
            for (int jt2 = 0; jt2 < 8; jt2++) {
                uint32_t addr = aKbase + (uint32_t)(
                    ((jt2*16 + (lane & 7) + ((lane >> 4) << 3))*QSTR
                     + (((lane >> 3) & 1) << 3) + ks*16) * 2);
                asm volatile("ldmatrix.sync.aligned.m8n8.x4.shared.b16 {%0,%1,%2,%3}, [%4];"
                    : "=r"(bk[2*jt2][0]), "=r"(bk[2*jt2][1]),
                      "=r"(bk[2*jt2+1][0]), "=r"(bk[2*jt2+1][1]) : "r"(addr));
            }
#pragma unroll
            for (int jt = 0; jt < 16; jt++) mma16816h(sacc[jt], aqh, bk[jt]);
#pragma unroll
            for (int jt = 0; jt < 16; jt++) mma16816h(sacc[jt], aql, bk[jt]);
        }

        // ---- bias + online softmax (rows fully in-warp) ----
        float mx0 = -1e30f, mx1 = -1e30f;
#pragma unroll
        for (int jt = 0; jt < 16; jt++) {
            int jbase = j0 + jt*8 + (lane & 3)*2;
#pragma unroll
            for (int c = 0; c < 2; c++) {
                int jg = jbase + c;
                float ukv = uks[jg];
                {
                    int dd = jg - ig0;
                    int a = dd < 0 ? -dd : dd;
                    int t = ts[a];
                    float ss = SsS[il0*33 + t];
                    float bias = SuS[il0*33 + t] + (dd > 0 ? ss : (dd < 0 ? -ss : 0.f)) + ukv;
                    float v = (sacc[jt][c] + bias) * scale;
                    sacc[jt][c] = v; mx0 = fmaxf(mx0, v);
                }
                {
                    int dd = jg - ig1;
                    int a = dd < 0 ? -dd : dd;
                    int t = ts[a];
                    float ss = SsS[(il0+8)*33 + t];
                    float bias = SuS[(il0+8)*33 + t] + (dd > 0 ? ss : (dd < 0 ? -ss : 0.f)) + ukv;
                    float v = (sacc[jt][2+c] + bias) * scale;
                    sacc[jt][2+c] = v; mx1 = fmaxf(mx1, v);
                }
            }
        }
        mx0 = fmaxf(mx0, __shfl_xor_sync(0xffffffffu, mx0, 1));
        mx0 = fmaxf(mx0, __shfl_xor_sync(0xffffffffu, mx0, 2));
        mx1 = fmaxf(mx1, __shfl_xor_sync(0xffffffffu, mx1, 1));
        mx1 = fmaxf(mx1, __shfl_xor_sync(0xffffffffu, mx1, 2));

        float mn0 = fmaxf(m0_, mx0), mn1 = fmaxf(m1_, mx1);
        float al0 = __expf(m0_ - mn0), al1 = __expf(m1_ - mn1);
        float rs0 = 0.f, rs1 = 0.f;
#pragma unroll
        for (int jt = 0; jt < 16; jt++) {
            float p0 = __expf(sacc[jt][0] - mn0);
            float p1 = __expf(sacc[jt][1] - mn0);
            float p2 = __expf(sacc[jt][2] - mn1);
            float p3 = __expf(sacc[jt][3] - mn1);
            sacc[jt][0] = p0; sacc[jt][1] = p1; sacc[jt][2] = p2; sacc[jt][3] = p3;
            rs0 += p0 + p1; rs1 += p2 + p3;
        }
        rs0 += __shfl_xor_sync(0xffffffffu, rs0, 1);
        rs0 += __shfl_xor_sync(0xffffffffu, rs0, 2);
        rs1 += __shfl_xor_sync(0xffffffffu, rs1, 1);
        rs1 += __shfl_xor_sync(0xffffffffu, rs1, 2);
        l0_ = l0_*al0 + rs0; l1_ = l1_*al1 + rs1;
        m0_ = mn0; m1_ = mn1;
#pragma unroll
        for (int d = 0; d < 8; d++) {
            oacc[d][0] *= al0; oacc[d][1] *= al0;
            oacc[d][2] *= al1; oacc[d][3] *= al1;
        }

        // ---- O += Ph @ (Vh + Vl)  (fp16-rounded P, exact V) ----
        // A-frag: a0=(r,k), a1=(r+8,k), a2=(r,k+8), a3=(r+8,k+8) — native order.
        uint32_t vHb = (uint32_t)__cvta_generic_to_shared(sVh);
        uint32_t vLb = (uint32_t)__cvta_generic_to_shared(sVl);
#pragma unroll
        for (int g = 0; g < 8; g++) {
            uint32_t aph[4];
#pragma unroll
            for (int q = 0; q < 4; q++) {
                int jt = 2*g + (q >> 1);
                int eb = (q & 1) * 2;
                __half2 hp = __floats2half2_rn(sacc[jt][eb], sacc[jt][eb+1]);
                aph[q] = *(uint32_t*)&hp;
            }

            uint32_t bv[8][2];
#pragma unroll
            for (int dt2 = 0; dt2 < 4; dt2++) {
                uint32_t addr = vHb + (uint32_t)(
                    ((dt2*16 + (lane & 7) + ((lane >> 4) << 3))*VSTR
                     + (((lane >> 3) & 1) << 3) + g*16) * 2);
                asm volatile("ldmatrix.sync.aligned.m8n8.x4.shared.b16 {%0,%1,%2,%3}, [%4];"
                    : "=r"(bv[2*dt2][0]), "=r"(bv[2*dt2][1]),
                      "=r"(bv[2*dt2+1][0]), "=r"(bv[2*dt2+1][1]) : "r"(addr));
            }
#pragma unroll
            for (int dt = 0; dt < 8; dt++) mma16816h(oacc[dt], aph, bv[dt]);
#pragma unroll
            for (int dt2 = 0; dt2 < 4; dt2++) {
                uint32_t addr = vLb + (uint32_t)(
                    ((dt2*16 + (lane & 7) + ((lane >> 4) << 3))*VSTR
                     + (((lane >> 3) & 1) << 3) + g*16) * 2);
                asm volatile("ldmatrix.sync.aligned.m8n8.x4.shared.b16 {%0,%1,%2,%3}, [%4];"
                    : "=r"(bv[2*dt2][0]), "=r"(bv[2*dt2][1]),
                      "=r"(bv[2*dt2+1][0]), "=r"(bv[2*dt2+1][1]) : "r"(addr));
            }
#pragma unroll
            for (int dt = 0; dt < 8; dt++) mma16816h(oacc[dt], aph, bv[dt]);
        }
    }

    // ---- epilogue: normalize, write bf16 hi|lo|hi aug directly ----
    float inv0 = 1.f / l0_, inv1 = 1.f / l1_;
    int row0 = b*NL + ig0;   // global AO row for slot 0
    int colb = hh*64 + (lane & 3)*2;
#pragma unroll
    for (int dt = 0; dt < 8; dt++) {
        int col = colb + dt*8;
        float o0 = oacc[dt][0]*inv0, o1 = oacc[dt][1]*inv0;
        float o2 = oacc[dt][2]*inv1, o3 = oacc[dt][3]*inv1;
        __nv_bfloat16 h0, l0v, h1, l1v, h2, l2v, h3, l3v;
        split_hl(o0, h0, l0v); split_hl(o1, h1, l1v);
        split_hl(o2, h2, l2v); split_hl(o3, h3, l3v);
        __nv_bfloat16* base0 = g_AOaug + (size_t)row0 * KAUG_O + col;
        __nv_bfloat16* base1 = g_AOaug + (size_t)(row0 + 8) * KAUG_O + col;
        *(__nv_bfloat162*)(base0)        = __nv_bfloat162(h0, h1);
        *(__nv_bfloat162*)(base0 + 512)  = __nv_bfloat162(l0v, l1v);
        *(__nv_bfloat162*)(base0 + 1024) = __nv_bfloat162(h0, h1);
        *(__nv_bfloat162*)(base1)        = __nv_bfloat162(h2, h3);
        *(__nv_bfloat162*)(base1 + 512)  = __nv_bfloat162(l2v, l3v);
        *(__nv_bfloat162*)(base1 + 1024) = __nv_bfloat162(h2, h3);
    }
}

// ----------------------------------------------------------------------------
extern "C" void kernel_launch(void* const* d_in, const int* in_sizes, int n_in,
                              void* d_out, int out_size)
{
    const float* x      = (const float*)d_in[0];
    const float* Wq     = (const float*)d_in[1];
    const float* Wk     = (const float*)d_in[2];
    const float* Wv     = (const float*)d_in[3];
    const float* Wo     = (const float*)d_in[4];
    const float* bo     = (const float*)d_in[5];
    const float* u_bias = (const float*)d_in[6];
    const float* v_bias = (const float*)d_in[7];
    const float* w_pos  = (const float*)d_in[8];
    float* out = (float*)d_out;

    cudaFuncSetAttribute(attn_kernel,
                         cudaFuncAttributeMaxDynamicSharedMemorySize, ATTN_SMEM);

    fold_w2_kernel<<<512, 256>>>(Wq, w_pos);
    conv_w_kernel<<<2048, 256>>>(Wq, Wk, Wv);
    conv_x_kernel<<<2048, 256>>>(x);
    prep_kernel<<<12, 256>>>(v_bias, w_pos);
    conv_wo_kernel<<<768, 256>>>(Wo);

    gemm_mma<<<dim3(16, 16), 256>>>(0, nullptr, nullptr);   // fused QKV|QW

    uksuf_kernel<<<4160, 256>>>(u_bias);
    attn_kernel<<<dim3(8, 8, 2), 256, ATTN_SMEM>>>();

    gemm_mma<<<dim3(6, 16), 256>>>(1, bo, out);             // out proj
}

// round 12
// speedup vs baseline: 2.4224x; 1.2964x over previous
#include <cuda_runtime.h>
#include <cuda_bf16.h>
#include <cuda_fp16.h>
#include <math.h>
#include <stdint.h>

#define NB 2
#define NL 1024
#define NH 8
#define ND 64
#define NDM 768
#define HD 512        /* NH*ND */
#define QLD 2048      /* g_qkv row stride: Q|K|V|QW */
#define KAUG_X 1536   /* 2*768: [x_hi | x_lo] vs [w_hi | w_hi] */
#define KAUG_O 1024   /* 2*512 */

// ------------------------- device scratch (no allocation) --------------------
static __device__ __align__(16) __half g_Aaug [NB*NL*KAUG_X];   // x hi|lo (fp16)
static __device__ __align__(16) __half g_Waug [2048*KAUG_X];    // Wq|Wk|Wv|W2 hi|hi
static __device__ __align__(16) __half g_AOaug[NB*NL*KAUG_O];   // attn out hi|lo
static __device__ __align__(16) __half g_WOaug[NDM*KAUG_O];     // Wo hi|hi
static __device__ __align__(16) float g_W2 [HD*NDM];            // folded Wq^T@wpos
static __device__ __align__(16) float g_qkv[NB*NL*QLD];         // K|QW fp32 regions used
// fp16 attention operands, [b][h][tok][d] (Q,K) and [b][h][d][tok] (V^T)
static __device__ __align__(16) __half g_qh[NB*NH*NL*ND];
static __device__ __align__(16) __half g_ql[NB*NH*NL*ND];
static __device__ __align__(16) __half g_kh[NB*NH*NL*ND];
static __device__ __align__(16) __half g_vth[NB*NH*ND*NL];
static __device__ __align__(16) __half g_vtl[NB*NH*ND*NL];
static __device__ __align__(16) float g_uk [NB*NH*NL];
static __device__ __align__(16) float g_Su [NB*NH*NL*33];
static __device__ __align__(16) float g_Ss [NB*NH*NL*33];
static __device__ __align__(16) float g_VrU[NH*33];
static __device__ __align__(16) float g_VrS[NH*33];
static __device__ int   g_t[NL];

// ------------------------- helpers -------------------------------------------
__device__ __forceinline__ void split_hl16(float v, __half& h, __half& l) {
    h = __float2half(v);
    l = __float2half(v - __half2float(h));
}

// -------- merged pre-kernel: fold_w2 | prep | conv_x | conv_wo ---------------
// blocks [0,512): W2 fold; [512,524): prep; [524,2572): conv_x; [2572,3340): conv_wo
__global__ void pre_kernel(const float* __restrict__ Wq,
                           const float* __restrict__ w_pos,
                           const float* __restrict__ v_bias,
                           const float* __restrict__ x,
                           const float* __restrict__ Wo)
{
    const int tid = threadIdx.x;
    const int blk = blockIdx.x;

    if (blk < 512) {                       // ---- fold_w2 ----
        __shared__ float wp[64];
        int hn = blk, h = hn >> 6, n = hn & 63;
        if (tid < 64) wp[tid] = w_pos[h*4096 + tid*64 + n];
        __syncthreads();
        for (int m = tid; m < NDM; m += 256) {
            float s = 0.f;
#pragma unroll 16
            for (int d = 0; d < 64; d++)
                s += Wq[(size_t)(h*64 + d)*NDM + m] * wp[d];
            g_W2[(size_t)hn*NDM + m] = s;
        }
        return;
    }
    if (blk < 524) {                       // ---- prep ----
        int sub = blk - 512;
        if (sub < 4) {
            __shared__ float cw[32];
            if (tid < 32) {
                float pr = expf(logf((float)(NL+1) * 0.5f) / 32.f);
                cw[tid] = powf(pr, (float)(tid+1));
            }
            __syncthreads();
            int a = sub*256 + tid;
            int t = 32;
            for (int f = 0; f < 32; f++)
                if ((float)a <= cw[f]) { t = f; break; }
            g_t[a] = t;
            return;
        }
        int hh = sub - 4;
        __shared__ float vws[64];
        if (tid < 64) {
            int n = tid;
            float s = 0.f;
            for (int d = 0; d < 64; d++)
                s += v_bias[hh*64 + d] * w_pos[hh*4096 + d*64 + n];
            vws[n] = s;
        }
        __syncthreads();
        if (tid < 2) {
            int half = tid;
            float* dst = (half ? g_VrS : g_VrU) + hh*33;
            const float* src = vws + half*32;
            float run = 0.f;
            dst[32] = 0.f;
            for (int f = 31; f >= 0; f--) { run += src[f]; dst[f] = run; }
        }
        return;
    }
    if (blk < 2572) {                      // ---- conv_x ----
        int row = blk - 524;
        const float* src = x + (size_t)row * NDM;
        __half* dst = g_Aaug + (size_t)row * KAUG_X;
        for (int c = tid; c < NDM; c += 256) {
            __half h, l; split_hl16(src[c], h, l);
            dst[c] = h; dst[NDM + c] = l;
        }
        return;
    }
    {                                      // ---- conv_wo ----
        int r = blk - 2572;
        const float* src = Wo + (size_t)r * HD;
        __half* dst = g_WOaug + (size_t)r * KAUG_O;
        for (int c = tid; c < HD; c += 256) {
            __half h = __float2half(src[c]);
            dst[c] = h; dst[HD + c] = h;
        }
    }
}

__global__ void conv_w_kernel(const float* __restrict__ Wq,
                              const float* __restrict__ Wk,
                              const float* __restrict__ Wv) {  // grid 2048
    int r = blockIdx.x;
    const float* src;
    if (r < 512)        src = Wq + (size_t)r * NDM;
    else if (r < 1024)  src = Wk + (size_t)(r-512) * NDM;
    else if (r < 1536)  src = Wv + (size_t)(r-1024) * NDM;
    else                src = g_W2 + (size_t)(r-1536) * NDM;
    __half* dst = g_Waug + (size_t)r * KAUG_X;
    for (int c = threadIdx.x; c < NDM; c += 256) {
        __half h = __float2half(src[c]);
        dst[c] = h; dst[NDM + c] = h;
    }
}

// ------------------------- mma.sync fp16 GEMM: C = A @ Bw^T ------------------
#define BM 128
#define BN 128
#define BK 32
#define GSTR 40

__device__ __forceinline__ void mma16816h(float* c, const uint32_t* a, const uint32_t* b) {
    asm volatile(
        "mma.sync.aligned.m16n8k16.row.col.f32.f16.f16.f32 "
        "{%0,%1,%2,%3}, {%4,%5,%6,%7}, {%8,%9}, {%0,%1,%2,%3};"
        : "+f"(c[0]), "+f"(c[1]), "+f"(c[2]), "+f"(c[3])
        : "r"(a[0]), "r"(a[1]), "r"(a[2]), "r"(a[3]), "r"(b[0]), "r"(b[1]));
}

__global__ __launch_bounds__(256, 1)
void gemm_mma(int which, const float* __restrict__ bias, float* __restrict__ Cout)
{
    __shared__ __half sA[2][BM*GSTR];
    __shared__ __half sB[2][BN*GSTR];

    const int tid = threadIdx.x;
    const int wid = tid >> 5, lane = tid & 31;
    const int wm = wid >> 2, wn = wid & 3;
    const int m0 = blockIdx.y * BM, n0 = blockIdx.x * BN;

    const __half *A, *Bw;
    float* C; int Kaug, Ntot;
    if (which == 0) { A = g_Aaug;  Bw = g_Waug;  C = g_qkv; Kaug = KAUG_X; Ntot = QLD; }
    else            { A = g_AOaug; Bw = g_WOaug; C = Cout;  Kaug = KAUG_O; Ntot = NDM; }
    const int nk = Kaug / BK;

    const int ldrow = tid >> 2, ldg = tid & 3;

    auto prefetch = [&](int c) {
        int p = c & 1;
        {
            const __half* Ab = A + (size_t)(m0 + ldrow) * Kaug + c*BK + ldg*8;
#pragma unroll
            for (int s = 0; s < 2; s++) {
                uint32_t dst = (uint32_t)__cvta_generic_to_shared(
                    &sA[p][(ldrow + s*64)*GSTR + ldg*8]);
                const void* src = Ab + (size_t)(s*64) * Kaug;
                asm volatile("cp.async.cg.shared.global [%0], [%1], 16;" :: "r"(dst), "l"(src));
            }
        }
        {
            const __half* Bb = Bw + (size_t)(n0 + ldrow) * Kaug + c*BK + ldg*8;
#pragma unroll
            for (int s = 0; s < 2; s++) {
                uint32_t dst = (uint32_t)__cvta_generic_to_shared(
                    &sB[p][(ldrow + s*64)*GSTR + ldg*8]);
                const void* src = Bb + (size_t)(s*64) * Kaug;
                asm volatile("cp.async.cg.shared.global [%0], [%1], 16;" :: "r"(dst), "l"(src));
            }
        }
        asm volatile("cp.async.commit_group;" ::: "memory");
    };

    float acc[4][4][4];
#pragma unroll
    for (int i = 0; i < 4; i++)
#pragma unroll
        for (int j = 0; j < 4; j++)
#pragma unroll
            for (int r = 0; r < 4; r++) acc[i][j][r] = 0.f;

    prefetch(0);

    for (int c = 0; c < nk; c++) {
        int p = c & 1;
        if (c + 1 < nk) {
            prefetch(c + 1);
            asm volatile("cp.async.wait_group 1;" ::: "memory");
        } else {
            asm volatile("cp.async.wait_group 0;" ::: "memory");
        }
        __syncthreads();

        uint32_t aB = (uint32_t)__cvta_generic_to_shared(&sA[p][0]);
        uint32_t bB = (uint32_t)__cvta_generic_to_shared(&sB[p][0]);

#pragma unroll
        for (int ks = 0; ks < 2; ks++) {
            uint32_t a[4][4];
#pragma unroll
            for (int i = 0; i < 4; i++) {
                uint32_t addr = aB + (uint32_t)(
                    ((wm*64 + i*16 + (lane & 15))*GSTR + ((lane >> 4)*8) + ks*16) * 2);
                asm volatile("ldmatrix.sync.aligned.m8n8.x4.shared.b16 {%0,%1,%2,%3}, [%4];"
                    : "=r"(a[i][0]), "=r"(a[i][1]), "=r"(a[i][2]), "=r"(a[i][3]) : "r"(addr));
            }
            uint32_t b[4][2];
#pragma unroll
            for (int jp = 0; jp < 2; jp++) {
                uint32_t addr = bB + (uint32_t)(
                    ((wn*32 + jp*16 + (lane & 7) + ((lane >> 4) << 3))*GSTR
                     + (((lane >> 3) & 1) << 3) + ks*16) * 2);
                asm volatile("ldmatrix.sync.aligned.m8n8.x4.shared.b16 {%0,%1,%2,%3}, [%4];"
                    : "=r"(b[2*jp][0]), "=r"(b[2*jp][1]),
                      "=r"(b[2*jp+1][0]), "=r"(b[2*jp+1][1]) : "r"(addr));
            }
#pragma unroll
            for (int i = 0; i < 4; i++)
#pragma unroll
                for (int j = 0; j < 4; j++)
                    mma16816h(acc[i][j], a[i], b[j]);
        }
        __syncthreads();
    }

    // epilogue
    if (which == 1) {
#pragma unroll
        for (int i = 0; i < 4; i++) {
            int r0 = m0 + wm*64 + i*16 + (lane >> 2);
#pragma unroll
            for (int j = 0; j < 4; j++) {
                int col = n0 + wn*32 + j*8 + (lane & 3)*2;
                float b0 = bias[col], b1 = bias[col+1];
                *(float2*)(C + (size_t)r0 * Ntot + col) =
                    make_float2(acc[i][j][0] + b0, acc[i][j][1] + b1);
                *(float2*)(C + (size_t)(r0 + 8) * Ntot + col) =
                    make_float2(acc[i][j][2] + b0, acc[i][j][3] + b1);
            }
        }
        return;
    }

    // which == 0: scatter into fp32 (K,QW regions) + fp16 attention operands
    auto emit = [&](int row, int col, float v0, float v1) {
        int reg = col >> 9;
        int bb = row >> 10, tok = row & 1023;
        int h = (col >> 6) & 7, d = col & 63;
        if (reg == 1 || reg == 3)
            *(float2*)(g_qkv + (size_t)row*QLD + col) = make_float2(v0, v1);
        if (reg == 3) return;
        __half h0, l0, h1, l1;
        split_hl16(v0, h0, l0); split_hl16(v1, h1, l1);
        if (reg == 2) {
            size_t vk = ((size_t)((bb*8+h)*64 + d))*1024 + tok;
            g_vth[vk] = h0; g_vtl[vk] = l0;
            g_vth[vk + 1024] = h1; g_vtl[vk + 1024] = l1;
            return;
        }
        size_t qk = ((size_t)((bb*8+h)*1024 + tok))*64 + d;
        if (reg == 0) {
            *(__half2*)(g_qh + qk) = __half2(h0, h1);
            *(__half2*)(g_ql + qk) = __half2(l0, l1);
        } else {
            *(__half2*)(g_kh + qk) = __half2(h0, h1);
        }
    };
#pragma unroll
    for (int i = 0; i < 4; i++) {
        int r0 = m0 + wm*64 + i*16 + (lane >> 2);
#pragma unroll
        for (int j = 0; j < 4; j++) {
            int col = n0 + wn*32 + j*8 + (lane & 3)*2;
            emit(r0,     col, acc[i][j][0], acc[i][j][1]);
            emit(r0 + 8, col, acc[i][j][2], acc[i][j][3]);
        }
    }
}

// -------- merged: suffix sums of qw rows (+vr) AND uk dot products -----------
__global__ __launch_bounds__(256)
void uksuf_kernel(const float* __restrict__ u_bias)
{
    if (blockIdx.x < 4096) {
        int gw = blockIdx.x*8 + (threadIdx.x >> 5);
        int lane = threadIdx.x & 31;
        int half = gw & 1;
        int pair = gw >> 1;
        int h = pair & 7;
        int row = pair >> 3;
        int b = row >> 10, i = row & 1023;

        float v = g_qkv[(size_t)row*QLD + 1536 + h*64 + half*32 + lane];
#pragma unroll
        for (int o = 1; o < 32; o <<= 1) {
            float t = __shfl_down_sync(0xffffffffu, v, o);
            if (lane + o < 32) v += t;
        }
        const float* vr = (half ? g_VrS : g_VrU) + h*33;
        float* dst = (half ? g_Ss : g_Su) + (size_t)((b*NH + h)*NL + i)*33;
        dst[lane] = v + vr[lane];
        if (lane == 0) dst[32] = vr[32];
        return;
    }
    int idx = (blockIdx.x - 4096)*256 + threadIdx.x;   // 0..16383
    int bh = idx >> 10, j = idx & 1023;
    int b = bh >> 3, hh = bh & 7;
    const float* kr = g_qkv + (size_t)(b*NL + j)*QLD + 512 + hh*ND;
    const float* ub = u_bias + hh*ND;
    float s = 0.f;
#pragma unroll
    for (int d = 0; d < ND; d += 4) {
        float4 kv = *(const float4*)(kr + d);
        float4 uv = *(const float4*)(ub + d);
        s += kv.x*uv.x + kv.y*uv.y + kv.z*uv.z + kv.w*uv.w;
    }
    g_uk[idx] = s;
}

// ---------------- flash attention, fp16 HMMA, factored rel-pos bias ----------
#define QSTR 72    /* Q/K smem row stride (fp16): 144B, 144%128=16 -> conflict-free */
#define VSTR 136   /* V^T smem row stride: 272B, %128=16 */
#define AOFF_QH 0
#define AOFF_QL (AOFF_QH + 128*QSTR*2)
#define AOFF_KH (AOFF_QL + 128*QSTR*2)
#define AOFF_VH (AOFF_KH + 128*QSTR*2)
#define AOFF_VL (AOFF_VH + 64*VSTR*2)
#define AOFF_SU (AOFF_VL + 64*VSTR*2)
#define AOFF_SS (AOFF_SU + 128*33*4)
#define AOFF_UK (AOFF_SS + 128*33*4)
#define AOFF_TS (AOFF_UK + 1024*4)
#define ATTN_SMEM (AOFF_TS + 1024*4)

__global__ __launch_bounds__(256, 1)
void attn_kernel()
{
    extern __shared__ char smc[];
    __half* sQh = (__half*)(smc + AOFF_QH);
    __half* sQl = (__half*)(smc + AOFF_QL);
    __half* sKh = (__half*)(smc + AOFF_KH);
    __half* sVh = (__half*)(smc + AOFF_VH);
    __half* sVl = (__half*)(smc + AOFF_VL);
    float* SuS = (float*)(smc + AOFF_SU);
    float* SsS = (float*)(smc + AOFF_SS);
    float* uks = (float*)(smc + AOFF_UK);
    int*   ts  = (int*)(smc + AOFF_TS);

    const int tid = threadIdx.x;
    const int wid = tid >> 5, lane = tid & 31;
    const int it = blockIdx.x, hh = blockIdx.y, b = blockIdx.z;
    const int i0 = it * 128;
    const int bh = b*NH + hh;
    const float scale = 0.125f;

    const size_t qkbase = (size_t)(bh*NL) * ND;      // Q/K [tok][d]
    const size_t vtbase = (size_t)(bh*ND) * NL;      // V^T [d][tok]

    // prologue: Q tiles + tables
    for (int idx = tid; idx < 1024; idx += 256) {    // 128 rows x 8 chunks(16B)
        int row = idx >> 3, g = idx & 7;
        size_t src = qkbase + (size_t)(i0 + row)*ND + g*8;
        *(uint4*)(sQh + row*QSTR + g*8) = *(const uint4*)(g_qh + src);
        *(uint4*)(sQl + row*QSTR + g*8) = *(const uint4*)(g_ql + src);
    }
    for (int idx = tid; idx < 128*33; idx += 256) {
        SuS[idx] = g_Su[(size_t)(bh*NL + i0)*33 + idx];
        SsS[idx] = g_Ss[(size_t)(bh*NL + i0)*33 + idx];
    }
    for (int idx = tid; idx < NL; idx += 256) {
        uks[idx] = g_uk[bh*NL + idx];
        ts[idx]  = g_t[idx];
    }

    const int il0 = wid*16 + (lane >> 2);
    const int ig0 = i0 + il0, ig1 = ig0 + 8;

    float m0_ = -1e30f, m1_ = -1e30f, l0_ = 0.f, l1_ = 0.f;
    float oacc[8][4];
#pragma unroll
    for (int d = 0; d < 8; d++)
#pragma unroll
        for (int e = 0; e < 4; e++) oacc[d][e] = 0.f;

    for (int jc = 0; jc < 8; jc++) {
        const int j0 = jc * 128;
        __syncthreads();
        for (int idx = tid; idx < 1024; idx += 256) {
            int row = idx >> 3, g = idx & 7;
            size_t src = qkbase + (size_t)(j0 + row)*ND + g*8;
            *(uint4*)(sKh + row*QSTR + g*8) = *(const uint4*)(g_kh + src);
        }
        for (int idx = tid; idx < 1024; idx += 256) { // 64 d-rows x 16 chunks
            int d = idx >> 4, g = idx & 15;
            size_t src = vtbase + (size_t)d*NL + j0 + g*8;
            *(uint4*)(sVh + d*VSTR + g*8) = *(const uint4*)(g_vth + src);
            *(uint4*)(sVl + d*VSTR + g*8) = *(const uint4*)(g_vtl + src);
        }
        __syncthreads();

        // ---- S = (Qh + Ql) @ Kh^T  (exact Q, fp16-rounded K) ----
        float sacc[16][4];
#pragma unroll
        for (int jt = 0; jt < 16; jt++)
#pragma unroll
            for (int e = 0; e < 4; e++) sacc[jt][e] = 0.f;

        uint32_t aQbase = (uint32_t)__cvta_generic_to_shared(sQh);
        uint32_t aQlb   = (uint32_t)__cvta_generic_to_shared(sQl);
        uint32_t aKbase = (uint32_t)__cvta_generic_to_shared(sKh);

#pragma unroll
        for (int ks = 0; ks < 4; ks++) {
            uint32_t aqh[4], aql[4];
            {
                uint32_t addr = aQbase + (uint32_t)(
                    ((wid*16 + (lane & 15))*QSTR + (lane >> 4)*8 + ks*16) * 2);
                asm volatile("ldmatrix.sync.aligned.m8n8.x4.shared.b16 {%0,%1,%2,%3}, [%4];"
                    : "=r"(aqh[0]), "=r"(aqh[1]), "=r"(aqh[2]), "=r"(aqh[3]) : "r"(addr));
                addr = aQlb + (uint32_t)(
                    ((wid*16 + (lane & 15))*QSTR + (lane >> 4)*8 + ks*16) * 2);
                asm volatile("ldmatrix.sync.aligned.m8n8.x4.shared.b16 {%0,%1,%2,%3}, [%4];"
                    : "=r"(aql[0]), "=r"(aql[1]), "=r"(aql[2]), "=r"(aql[3]) : "r"(addr));
            }
            uint32_t bk[16][2];
#pragma unroll
            for (int jt2 = 0; jt2 < 8; jt2++) {
                uint32_t addr = aKbase + (uint32_t)(
                    ((jt2*16 + (lane & 7) + ((lane >> 4) << 3))*QSTR
                     + (((lane >> 3) & 1) << 3) + ks*16) * 2);
                asm volatile("ldmatrix.sync.aligned.m8n8.x4.shared.b16 {%0,%1,%2,%3}, [%4];"
                    : "=r"(bk[2*jt2][0]), "=r"(bk[2*jt2][1]),
                      "=r"(bk[2*jt2+1][0]), "=r"(bk[2*jt2+1][1]) : "r"(addr));
            }
#pragma unroll
            for (int jt = 0; jt < 16; jt++) mma16816h(sacc[jt], aqh, bk[jt]);
#pragma unroll
            for (int jt = 0; jt < 16; jt++) mma16816h(sacc[jt], aql, bk[jt]);
        }

        // ---- bias + online softmax (rows fully in-warp) ----
        float mx0 = -1e30f, mx1 = -1e30f;
#pragma unroll
        for (int jt = 0; jt < 16; jt++) {
            int jbase = j0 + jt*8 + (lane & 3)*2;
#pragma unroll
            for (int c = 0; c < 2; c++) {
                int jg = jbase + c;
                float ukv = uks[jg];
                {
                    int dd = jg - ig0;
                    int a = dd < 0 ? -dd : dd;
                    int t = ts[a];
                    float ss = SsS[il0*33 + t];
                    float bias = SuS[il0*33 + t] + (dd > 0 ? ss : (dd < 0 ? -ss : 0.f)) + ukv;
                    float v = (sacc[jt][c] + bias) * scale;
                    sacc[jt][c] = v; mx0 = fmaxf(mx0, v);
                }
                {
                    int dd = jg - ig1;
                    int a = dd < 0 ? -dd : dd;
                    int t = ts[a];
                    float ss = SsS[(il0+8)*33 + t];
                    float bias = SuS[(il0+8)*33 + t] + (dd > 0 ? ss : (dd < 0 ? -ss : 0.f)) + ukv;
                    float v = (sacc[jt][2+c] + bias) * scale;
                    sacc[jt][2+c] = v; mx1 = fmaxf(mx1, v);
                }
            }
        }
        mx0 = fmaxf(mx0, __shfl_xor_sync(0xffffffffu, mx0, 1));
        mx0 = fmaxf(mx0, __shfl_xor_sync(0xffffffffu, mx0, 2));
        mx1 = fmaxf(mx1, __shfl_xor_sync(0xffffffffu, mx1, 1));
        mx1 = fmaxf(mx1, __shfl_xor_sync(0xffffffffu, mx1, 2));

        float mn0 = fmaxf(m0_, mx0), mn1 = fmaxf(m1_, mx1);
        float al0 = __expf(m0_ - mn0), al1 = __expf(m1_ - mn1);
        float rs0 = 0.f, rs1 = 0.f;
#pragma unroll
        for (int jt = 0; jt < 16; jt++) {
            float p0 = __expf(sacc[jt][0] - mn0);
            float p1 = __expf(sacc[jt][1] - mn0);
            float p2 = __expf(sacc[jt][2] - mn1);
            float p3 = __expf(sacc[jt][3] - mn1);
            sacc[jt][0] = p0; sacc[jt][1] = p1; sacc[jt][2] = p2; sacc[jt][3] = p3;
            rs0 += p0 + p1; rs1 += p2 + p3;
        }
        rs0 += __shfl_xor_sync(0xffffffffu, rs0, 1);
        rs0 += __shfl_xor_sync(0xffffffffu, rs0, 2);
        rs1 += __shfl_xor_sync(0xffffffffu, rs1, 1);
        rs1 += __shfl_xor_sync(0xffffffffu, rs1, 2);
        l0_ = l0_*al0 + rs0; l1_ = l1_*al1 + rs1;
        m0_ = mn0; m1_ = mn1;
#pragma unroll
        for (int d = 0; d < 8; d++) {
            oacc[d][0] *= al0; oacc[d][1] *= al0;
            oacc[d][2] *= al1; oacc[d][3] *= al1;
        }

        // ---- O += Ph @ (Vh + Vl)  (fp16-rounded P, exact V) ----
        uint32_t vHb = (uint32_t)__cvta_generic_to_shared(sVh);
        uint32_t vLb = (uint32_t)__cvta_generic_to_shared(sVl);
#pragma unroll
        for (int g = 0; g < 8; g++) {
            uint32_t aph[4];
#pragma unroll
            for (int q = 0; q < 4; q++) {
                int jt = 2*g + (q >> 1);
                int eb = (q & 1) * 2;
                __half2 hp = __floats2half2_rn(sacc[jt][eb], sacc[jt][eb+1]);
                aph[q] = *(uint32_t*)&hp;
            }

            uint32_t bv[8][2];
#pragma unroll
            for (int dt2 = 0; dt2 < 4; dt2++) {
                uint32_t addr = vHb + (uint32_t)(
                    ((dt2*16 + (lane & 7) + ((lane >> 4) << 3))*VSTR
                     + (((lane >> 3) & 1) << 3) + g*16) * 2);
                asm volatile("ldmatrix.sync.aligned.m8n8.x4.shared.b16 {%0,%1,%2,%3}, [%4];"
                    : "=r"(bv[2*dt2][0]), "=r"(bv[2*dt2][1]),
                      "=r"(bv[2*dt2+1][0]), "=r"(bv[2*dt2+1][1]) : "r"(addr));
            }
#pragma unroll
            for (int dt = 0; dt < 8; dt++) mma16816h(oacc[dt], aph, bv[dt]);
#pragma unroll
            for (int dt2 = 0; dt2 < 4; dt2++) {
                uint32_t addr = vLb + (uint32_t)(
                    ((dt2*16 + (lane & 7) + ((lane >> 4) << 3))*VSTR
                     + (((lane >> 3) & 1) << 3) + g*16) * 2);
                asm volatile("ldmatrix.sync.aligned.m8n8.x4.shared.b16 {%0,%1,%2,%3}, [%4];"
                    : "=r"(bv[2*dt2][0]), "=r"(bv[2*dt2][1]),
                      "=r"(bv[2*dt2+1][0]), "=r"(bv[2*dt2+1][1]) : "r"(addr));
            }
#pragma unroll
            for (int dt = 0; dt < 8; dt++) mma16816h(oacc[dt], aph, bv[dt]);
        }
    }

    // ---- epilogue: normalize, write fp16 hi|lo aug directly ----
    float inv0 = 1.f / l0_, inv1 = 1.f / l1_;
    int row0 = b*NL + ig0;   // global AO row for slot 0
    int colb = hh*64 + (lane & 3)*2;
#pragma unroll
    for (int dt = 0; dt < 8; dt++) {
        int col = colb + dt*8;
        float o0 = oacc[dt][0]*inv0, o1 = oacc[dt][1]*inv0;
        float o2 = oacc[dt][2]*inv1, o3 = oacc[dt][3]*inv1;
        __half h0, l0v, h1, l1v, h2, l2v, h3, l3v;
        split_hl16(o0, h0, l0v); split_hl16(o1, h1, l1v);
        split_hl16(o2, h2, l2v); split_hl16(o3, h3, l3v);
        __half* base0 = g_AOaug + (size_t)row0 * KAUG_O + col;
        __half* base1 = g_AOaug + (size_t)(row0 + 8) * KAUG_O + col;
        *(__half2*)(base0)       = __half2(h0, h1);
        *(__half2*)(base0 + 512) = __half2(l0v, l1v);
        *(__half2*)(base1)       = __half2(h2, h3);
        *(__half2*)(base1 + 512) = __half2(l2v, l3v);
    }
}

// ----------------------------------------------------------------------------
extern "C" void kernel_launch(void* const* d_in, const int* in_sizes, int n_in,
                              void* d_out, int out_size)
{
    const float* x      = (const float*)d_in[0];
    const float* Wq     = (const float*)d_in[1];
    const float* Wk     = (const float*)d_in[2];
    const float* Wv     = (const float*)d_in[3];
    const float* Wo     = (const float*)d_in[4];
    const float* bo     = (const float*)d_in[5];
    const float* u_bias = (const float*)d_in[6];
    const float* v_bias = (const float*)d_in[7];
    const float* w_pos  = (const float*)d_in[8];
    float* out = (float*)d_out;

    cudaFuncSetAttribute(attn_kernel,
                         cudaFuncAttributeMaxDynamicSharedMemorySize, ATTN_SMEM);

    pre_kernel<<<3340, 256>>>(Wq, w_pos, v_bias, x, Wo);   // fold|prep|conv_x|conv_wo
    conv_w_kernel<<<2048, 256>>>(Wq, Wk, Wv);

    gemm_mma<<<dim3(16, 16), 256>>>(0, nullptr, nullptr);  // fused QKV|QW

    uksuf_kernel<<<4160, 256>>>(u_bias);
    attn_kernel<<<dim3(8, 8, 2), 256, ATTN_SMEM>>>();

    gemm_mma<<<dim3(6, 16), 256>>>(1, bo, out);            // out proj
}